// round 9
// baseline (speedup 1.0000x reference)
#include <cuda_runtime.h>
#include <cuda_bf16.h>
#include <cstdint>

constexpr int NB=4, NG=1024, NC=1024, NQ=256, FF=512, HH=8, DD=64;
constexpr size_t SZ_GF=(size_t)NB*NG*FF, SZ_QF=(size_t)NB*NQ*FF;
constexpr size_t O_G0=0,O_C0=O_G0+SZ_GF,O_Q0=O_C0+SZ_GF,O_G1=O_Q0+SZ_QF,O_GS=O_G1+SZ_GF;
constexpr size_t O_PJQ=O_GS+SZ_GF,O_PJK=O_PJQ+SZ_GF,O_AGG=O_PJK+SZ_GF;
constexpr size_t O_EQ=O_AGG+SZ_GF,O_EK=O_EQ+32768,O_Q1=O_EK+32768,O_K1=O_Q1+32768;
constexpr size_t O_Q2=O_K1+32768,O_K2=O_Q2+32768,O_CSC=O_K2+32768,O_PS=O_CSC+32768;
constexpr size_t O_BGC=O_PS+262144,O_BGQ=O_BGC+131072,O_BGQT=O_BGQ+32768;
constexpr size_t O_WTH=O_BGQT+32768,O_WTL=O_WTH+786432;
constexpr size_t O_FWH=O_WTL+786432,O_FWL=O_FWH+4194304;
constexpr size_t S_TOT=O_FWL+4194304;
__device__ float d_scratch[S_TOT];

__global__ void bitpack_k(const int* __restrict__ adj, unsigned* __restrict__ bits, int nwords){
    int w=blockIdx.x*256+threadIdx.x; if(w>=nwords) return;
    const int* p=adj+(size_t)w*32; unsigned v=0;
    #pragma unroll
    for(int i=0;i<32;i++) v|=(p[i]>0?1u:0u)<<i;
    bits[w]=v;
}
__global__ void bitpackT_k(const int* __restrict__ adj, unsigned* __restrict__ bits){
    int idx=blockIdx.x*256+threadIdx.x; if(idx>=NB*NQ*(NG/32)) return;
    int gw=idx&31, q=(idx>>5)&255, b=idx>>13;
    unsigned v=0;
    for(int i=0;i<32;i++) v|=(adj[((size_t)b*NG+gw*32+i)*NQ+q]>0?1u:0u)<<i;
    bits[(size_t)b*NQ*32+(size_t)q*32+gw]=v;
}
__global__ void repack3_k(const float* __restrict__ W0,const float* __restrict__ W1,
                          const float* __restrict__ W2, __nv_bfloat16* __restrict__ hi,
                          __nv_bfloat16* __restrict__ lo){
    int i=blockIdx.x*256+threadIdx.x; if(i>=3*2*HH*FF*DD) return;
    int tp=i>>19, j=i&524287;
    int d=j&63, f=(j>>6)&511, h=(j>>15)&7, l=j>>18;
    const float* W=tp==0?W0:(tp==1?W1:W2);
    float v=W[j];
    size_t o=(size_t)tp*2*FF*512+((size_t)(l*FF+f))*512+h*64+d;
    __nv_bfloat16 hh=__float2bfloat16_rn(v);
    hi[o]=hh; lo[o]=__float2bfloat16_rn(v-__bfloat162float(hh));
}
__global__ void wsplit_k(const float* __restrict__ in, __nv_bfloat16* __restrict__ hi,
                         __nv_bfloat16* __restrict__ lo, int n){
    int i=blockIdx.x*256+threadIdx.x; if(i>=n) return;
    float v=in[i];
    __nv_bfloat16 h=__float2bfloat16_rn(v);
    hi[i]=h; lo[i]=__float2bfloat16_rn(v-__bfloat162float(h));
}
__global__ void dot_a_k(const float* __restrict__ X, const float* __restrict__ a,
                        float* __restrict__ raw, float* __restrict__ e1, float* __restrict__ e2, int N){
    int idx=blockIdx.x*256+threadIdx.x; if(idx>=NB*HH*N) return;
    int n=idx%N, h=(idx/N)%HH, b=idx/(N*HH);
    const float* xp=X+((size_t)(b*N+n))*FF+h*DD; const float* ap=a+h*DD;
    float s=0.f;
    #pragma unroll
    for(int i=0;i<DD;i+=4){
        float4 xv=*(const float4*)(xp+i); float4 av=*(const float4*)(ap+i);
        s+=xv.x*av.x+xv.y*av.y+xv.z*av.z+xv.w*av.w;
    }
    raw[idx]=s; e1[idx]=__expf(s); e2[idx]=__expf(0.2f*s);
}
__global__ void bitsum_k(const unsigned* __restrict__ bits,
    const float* __restrict__ rq,const float* __restrict__ q1,const float* __restrict__ q2,
    const float* __restrict__ rk,const float* __restrict__ k1,const float* __restrict__ k2,
    float* __restrict__ ps, int Nn,int Mm,int bld,int nch,long long sb){
    __shared__ unsigned wb[32][4];
    __shared__ float qt[3][8][32];
    int t=threadIdx.x, m=blockIdx.x*128+t, b=blockIdx.z;
    int nbase=blockIdx.y*256;
    float acc[8]={}; float rkv[8],k1v[8],k2v[8];
    #pragma unroll
    for(int h=0;h<8;h++){ int bh=b*8+h; rkv[h]=rk[(size_t)bh*Mm+m]; k1v[h]=k1[(size_t)bh*Mm+m]; k2v[h]=k2[(size_t)bh*Mm+m]; }
    const unsigned* bb=bits+(size_t)b*sb+blockIdx.x*4;
    for(int n0=nbase;n0<nbase+256;n0+=32){
        wb[t>>2][t&3]=bb[(size_t)(n0+(t>>2))*bld+(t&3)];
        for(int i=t;i<768;i+=128){
            int which=i>>8, r=i&255, h=r>>5, nn=r&31;
            const float* src=which==0?rq:(which==1?q1:q2);
            qt[which][h][nn]=src[(size_t)(b*8+h)*Nn+n0+nn];
        }
        __syncthreads();
        int mw=t>>5, msh=t&31;
        for(int nn=0;nn<32;nn++){
            if((wb[nn][mw]>>msh)&1u){
                #pragma unroll
                for(int h=0;h<8;h++){
                    bool c=qt[0][h][nn]+rkv[h]>0.f;
                    acc[h]+= c? qt[1][h][nn]*k1v[h] : qt[2][h][nn]*k2v[h];
                }
            }
        }
        __syncthreads();
    }
    #pragma unroll
    for(int h=0;h<8;h++) ps[((size_t)(b*8+h)*Mm+m)*nch+blockIdx.y]=acc[h];
}
__global__ void csmerge_k(const float* __restrict__ ps, float* __restrict__ cs, int Mm, int nch){
    int idx=blockIdx.x*256+threadIdx.x; if(idx>=NB*HH*Mm) return;
    float s=0.f;
    for(int c=0;c<nch;c++) s+=ps[(size_t)idx*nch+c];
    cs[idx]=(s>0.f)?(1.f/s):0.f;
}

// ============ bf16-split mma.sync GEMM ============
struct GP {
    int M,N,K1,K2,Hdiv;
    const float *A1,*B1,*A2;
    int lda1,ldb1,lda2,ldc;
    float* C;
    const float *E2,*scv;
    const float *qr,*qe1,*qe2,*kr,*ke1,*ke2;
    const __nv_bfloat16 *BH[4],*BL[4];
    long long sA_b,sA_h,sB_b,sB_h,sC_b,sC_h,sSc;
    const unsigned* bits; int bld; long long sBits_b;
};
__device__ __forceinline__ void mma16816(float* c, const unsigned* a, const unsigned* b){
    asm volatile("mma.sync.aligned.m16n8k16.row.col.f32.bf16.bf16.f32 "
        "{%0,%1,%2,%3},{%4,%5,%6,%7},{%8,%9},{%0,%1,%2,%3};"
        : "+f"(c[0]),"+f"(c[1]),"+f"(c[2]),"+f"(c[3])
        : "r"(a[0]),"r"(a[1]),"r"(a[2]),"r"(a[3]),"r"(b[0]),"r"(b[1]));
}
#define LDSM4(d,a) asm volatile("ldmatrix.sync.aligned.m8n8.x4.shared.b16 {%0,%1,%2,%3},[%4];":"=r"((d)[0]),"=r"((d)[1]),"=r"((d)[2]),"=r"((d)[3]):"r"(a))
#define LDSM4T(d,a) asm volatile("ldmatrix.sync.aligned.m8n8.x4.trans.shared.b16 {%0,%1,%2,%3},[%4];":"=r"((d)[0]),"=r"((d)[1]),"=r"((d)[2]),"=r"((d)[3]):"r"(a))
#define SWZA(r,c) (((r)<<5)+((((c)>>3)^(((r)>>1)&3))<<3)+((c)&7))
#define SWZB(r,c) (((r)<<6)+((((c)>>3)^((r)&7))<<3)+((c)&7))
constexpr int A_H=128*32, B_H=32*64;

template<int ASRC,int EPI,int BPRE,int NBS>
__global__ void __launch_bounds__(256) gemm_k(GP p){
    extern __shared__ __nv_bfloat16 sm[];
    constexpr int SSTR=2*A_H+NBS*2*B_H;
    const int t=threadIdx.x, lane=t&31, wid=t>>5;
    const int wm=wid&3, wn=wid>>2, g=lane>>2, tc=lane&3;
    const int m0=blockIdx.x*128, n0=blockIdx.y*64, z=blockIdx.z;
    const int zb=z/p.Hdiv, zh=z%p.Hdiv;
    const float* B1=p.B1?(p.B1+zb*p.sB_b+zh*p.sB_h):nullptr;
    float* C=p.C+zb*p.sC_b+zh*p.sC_h;
    const float* A1=nullptr; const unsigned* bitsp=nullptr;
    if(ASRC==0) A1=p.A1+zb*p.sA_b+zh*p.sA_h;
    else        bitsp=p.bits+zb*p.sBits_b;
    const float* scv=(ASRC==2)?(p.scv+(long long)z*p.sSc):nullptr;
    const int Ktot=p.K1+p.K2, niter=Ktot>>5;
    float acc[NBS][2][4][4]={};
    float rA[16], rB[8]; unsigned rW=0;
    uint4 rBH[NBS], rBL[NBS];
    const int ar=t>>1, akq=(t&1)*16;
    const int br=t>>3, bnq=(t&7)*8;
    const int wk=t&31, wsel=t>>5;
    float rqv=0.f,q1v=0.f,q2v=0.f;
    float* kt=(float*)(sm+2*SSTR);
    unsigned smb=(unsigned)__cvta_generic_to_shared(sm);
    unsigned aAddr[2][2], bAddr[NBS][2][2];
    {
        int rA_=wm*32+(lane&15), cgA=(lane>>4)*8;
        #pragma unroll
        for(int mt=0;mt<2;mt++)
            #pragma unroll
            for(int k2=0;k2<2;k2++) aAddr[mt][k2]=smb+2u*SWZA(rA_+mt*16, cgA+k2*16);
        int rB_=(lane&7)+((lane>>3)&1)*8, cB=wn*32+(lane>>4)*8;
        #pragma unroll
        for(int s=0;s<NBS;s++)
            #pragma unroll
            for(int pp=0;pp<2;pp++)
                #pragma unroll
                for(int k2=0;k2<2;k2++)
                    bAddr[s][pp][k2]=smb+2u*(2*A_H+s*2*B_H+SWZB(rB_+k2*16, cB+pp*16));
    }
    if(ASRC==2){
        long long qo=(long long)z*p.M; int n=m0+ar;
        rqv=p.qr[qo+n]; q1v=p.qe1[qo+n]; q2v=p.qe2[qo+n];
        long long ko=(long long)z*p.K1;
        for(int i=t;i<p.K1;i+=256){
            kt[i]=p.kr[ko+i]; kt[p.K1+i]=p.ke1[ko+i]; kt[2*p.K1+i]=p.ke2[ko+i];
        }
        __syncthreads();
    }
    auto loadregs=[&](int it){
        int kk=it<<5;
        if(ASRC==0){
            const float* Ap; int ldA,ko;
            if(kk<p.K1){Ap=A1; ldA=p.lda1; ko=kk;} else {Ap=p.A2; ldA=p.lda2; ko=kk-p.K1;}
            const float* s=Ap+(long long)(m0+ar)*ldA+ko+akq;
            #pragma unroll
            for(int q=0;q<4;q++) *(float4*)(rA+q*4)=*(const float4*)(s+q*4);
        } else if(ASRC==1){
            rW=bitsp[(long long)(kk+wk)*p.bld+((unsigned)m0>>5)+(wsel>>1)];
        } else {
            rW=bitsp[(size_t)(m0+ar)*p.bld+(kk>>5)];
        }
        if(BPRE){
            int sec=(kk>=p.K1)?1:0, ko=sec?kk-p.K1:kk;
            long long off=(long long)(ko+br)*512+n0+bnq;
            #pragma unroll
            for(int s=0;s<NBS;s++){
                rBH[s]=*(const uint4*)(p.BH[s*2+sec]+off);
                rBL[s]=*(const uint4*)(p.BL[s*2+sec]+off);
            }
        } else {
            const float* s=B1+(long long)(kk+br)*p.ldb1+n0+bnq;
            *(float4*)(rB)=*(const float4*)(s);
            *(float4*)(rB+4)=*(const float4*)(s+4);
            if(ASRC==2){
                float scl=scv[kk+br];
                #pragma unroll
                for(int i=0;i<8;i++) rB[i]*=scl;
            }
        }
    };
    auto storesm=[&](int buf,int kk){
        __nv_bfloat16* base=sm+buf*SSTR;
        if(ASRC==0){
            #pragma unroll
            for(int i=0;i<16;i+=2){
                float x0=rA[i], x1=rA[i+1];
                __nv_bfloat16 h0=__float2bfloat16_rn(x0), h1=__float2bfloat16_rn(x1);
                __nv_bfloat16 l0=__float2bfloat16_rn(x0-__bfloat162float(h0));
                __nv_bfloat16 l1=__float2bfloat16_rn(x1-__bfloat162float(h1));
                int o=SWZA(ar,akq+i);
                *(__nv_bfloat162*)(base+o)=__nv_bfloat162(h0,h1);
                *(__nv_bfloat162*)(base+A_H+o)=__nv_bfloat162(l0,l1);
            }
        } else if(ASRC==1){
            int mb=wsel*16, sh=(wsel&1)*16;
            #pragma unroll
            for(int i=0;i<16;i++)
                base[SWZA(mb+i,wk)]=__float2bfloat16_rn((float)((rW>>(sh+i))&1u));
        } else {
            #pragma unroll
            for(int i=0;i<16;i++){
                float v=0.f;
                if((rW>>(akq+i))&1u){
                    int mI=kk+akq+i;
                    v=(rqv+kt[mI]>0.f)?(q1v*kt[p.K1+mI]):(q2v*kt[2*p.K1+mI]);
                }
                __nv_bfloat16 h=__float2bfloat16_rn(v);
                int o=SWZA(ar,akq+i);
                base[o]=h; base[A_H+o]=__float2bfloat16_rn(v-__bfloat162float(h));
            }
        }
        int o=SWZB(br,bnq);
        if(BPRE){
            #pragma unroll
            for(int s=0;s<NBS;s++){
                *(uint4*)(base+2*A_H+s*2*B_H+o)=rBH[s];
                *(uint4*)(base+2*A_H+s*2*B_H+B_H+o)=rBL[s];
            }
        } else {
            __nv_bfloat162 hp[4], lp[4];
            #pragma unroll
            for(int j=0;j<4;j++){
                float x0=rB[2*j], x1=rB[2*j+1];
                __nv_bfloat16 h0=__float2bfloat16_rn(x0), h1=__float2bfloat16_rn(x1);
                hp[j]=__nv_bfloat162(h0,h1);
                lp[j]=__nv_bfloat162(__float2bfloat16_rn(x0-__bfloat162float(h0)),
                                     __float2bfloat16_rn(x1-__bfloat162float(h1)));
            }
            *(uint4*)(base+2*A_H+o)=*(uint4*)hp;
            *(uint4*)(base+2*A_H+B_H+o)=*(uint4*)lp;
        }
    };

    loadregs(0);
    for(int it=0;it<niter;it++){
        int buf=it&1;
        storesm(buf,it<<5);
        __syncthreads();
        if(it+1<niter) loadregs(it+1);
        unsigned bo=(unsigned)buf*SSTR*2u;
        #pragma unroll
        for(int k2=0;k2<2;k2++){
            unsigned aH[2][4], aL[2][4];
            #pragma unroll
            for(int mt=0;mt<2;mt++){
                LDSM4(aH[mt], aAddr[mt][k2]+bo);
                if(ASRC!=1) LDSM4(aL[mt], aAddr[mt][k2]+bo+2u*A_H);
            }
            #pragma unroll
            for(int s=0;s<NBS;s++){
                unsigned bH[2][4], bL[2][4];
                #pragma unroll
                for(int pp=0;pp<2;pp++){
                    LDSM4T(bH[pp], bAddr[s][pp][k2]+bo);
                    LDSM4T(bL[pp], bAddr[s][pp][k2]+bo+2u*B_H);
                }
                #pragma unroll
                for(int mt=0;mt<2;mt++)
                    #pragma unroll
                    for(int nt=0;nt<4;nt++){
                        const unsigned* bh=&bH[nt>>1][(nt&1)*2];
                        const unsigned* bl=&bL[nt>>1][(nt&1)*2];
                        mma16816(acc[s][mt][nt],aH[mt],bh);
                        mma16816(acc[s][mt][nt],aH[mt],bl);
                        if(ASRC!=1) mma16816(acc[s][mt][nt],aL[mt],bh);
                    }
            }
        }
        __syncthreads();
    }
    #pragma unroll
    for(int mt=0;mt<2;mt++)
        #pragma unroll
        for(int nt=0;nt<4;nt++)
            #pragma unroll
            for(int hrow=0;hrow<2;hrow++){
                long long r=m0+wm*32+mt*16+g+hrow*8;
                int col=n0+wn*32+nt*8+tc*2;
                float x0=acc[0][mt][nt][hrow*2], x1=acc[0][mt][nt][hrow*2+1];
                float2 o;
                if(EPI==1){
                    float2 a=*(const float2*)(p.E2+r*p.ldc+col);
                    float g0=acc[1][mt][nt][hrow*2], g1=acc[1][mt][nt][hrow*2+1];
                    float f;
                    f=1.f/(1.f+__expf(-g0)); o.x=a.x+f*(x0-a.x);
                    f=1.f/(1.f+__expf(-g1)); o.y=a.y+f*(x1-a.y);
                } else if(EPI==2){
                    o.x=x0>0.f?x0:__expf(x0)-1.f; o.y=x1>0.f?x1:__expf(x1)-1.f;
                } else { o.x=x0; o.y=x1; }
                *(float2*)(C+r*p.ldc+col)=o;
            }
}

constexpr int SMB1=2*(2*A_H+2*B_H)*2+12288;
constexpr int SMB2=2*(2*A_H+4*B_H)*2;

static void proj_go(const float* X,int rows,const __nv_bfloat16* WH,const __nv_bfloat16* WL,float* out){
    GP p{}; p.M=rows; p.N=512; p.K1=512; p.Hdiv=1;
    p.A1=X; p.lda1=512; p.BH[0]=WH; p.BL[0]=WL; p.C=out; p.ldc=512;
    gemm_k<0,0,1,1><<<dim3(rows/128,8,1),256,SMB1>>>(p);
}
static void fusion_go(const float* a,const float* bm,int rows,
                      const __nv_bfloat16* FWH,const __nv_bfloat16* FWL,size_t woff,float* out){
    GP p{}; p.M=rows; p.N=512; p.K1=512; p.K2=512; p.Hdiv=1;
    p.A1=a; p.lda1=512; p.A2=bm; p.lda2=512;
    p.BH[0]=FWH+0*2097152+woff; p.BH[1]=FWH+1*2097152+woff;
    p.BH[2]=FWH+2*2097152+woff; p.BH[3]=FWH+3*2097152+woff;
    p.BL[0]=FWL+0*2097152+woff; p.BL[1]=FWL+1*2097152+woff;
    p.BL[2]=FWL+2*2097152+woff; p.BL[3]=FWL+3*2097152+woff;
    p.E2=a; p.C=out; p.ldc=512;
    gemm_k<0,1,1,2><<<dim3(rows/128,8,1),256,SMB2>>>(p);
}
static void attn_go(float* S,const float* q,int Nqq,const float* kv,int Nkv,
                    const __nv_bfloat16* WH,const __nv_bfloat16* WL,
                    const float* a1,const float* a2,
                    const unsigned* bits,int bld,long long sb,float* agg){
    float *projQ=S+O_PJQ,*projK=S+O_PJK;
    float *rq=S+O_EQ,*rk=S+O_EK,*q1=S+O_Q1,*k1=S+O_K1,*q2=S+O_Q2,*k2=S+O_K2;
    float *cs=S+O_CSC,*ps=S+O_PS;
    proj_go(q,NB*Nqq,WH,WL,projQ);
    proj_go(kv,NB*Nkv,WH,WL,projK);
    dot_a_k<<<(NB*HH*Nqq+255)/256,256>>>(projQ,a1,rq,q1,q2,Nqq);
    dot_a_k<<<(NB*HH*Nkv+255)/256,256>>>(projK,a2,rk,k1,k2,Nkv);
    int nch=Nqq/256;
    bitsum_k<<<dim3(Nkv/128,nch,NB),128>>>(bits,rq,q1,q2,rk,k1,k2,ps,Nqq,Nkv,bld,nch,sb);
    csmerge_k<<<(NB*HH*Nkv+255)/256,256>>>(ps,cs,Nkv,nch);
    GP p{}; p.M=Nqq; p.N=64; p.K1=Nkv; p.Hdiv=HH;
    p.B1=projK; p.ldb1=512; p.sB_b=(long long)Nkv*512; p.sB_h=64;
    p.C=agg; p.ldc=512; p.sC_b=(long long)Nqq*512; p.sC_h=64;
    p.scv=cs; p.sSc=Nkv;
    p.qr=rq; p.qe1=q1; p.qe2=q2; p.kr=rk; p.ke1=k1; p.ke2=k2;
    p.bits=bits; p.bld=bld; p.sBits_b=sb;
    gemm_k<2,2,0,1><<<dim3(Nqq/128,1,NB*HH),256,SMB1>>>(p);
}

extern "C" void kernel_launch(void* const* d_in, const int* in_sizes, int n_in,
                              void* d_out, int out_size){
    cudaFuncSetAttribute(gemm_k<0,0,1,1>,cudaFuncAttributeMaxDynamicSharedMemorySize,SMB1);
    cudaFuncSetAttribute(gemm_k<0,1,1,2>,cudaFuncAttributeMaxDynamicSharedMemorySize,SMB2);
    cudaFuncSetAttribute(gemm_k<1,0,0,1>,cudaFuncAttributeMaxDynamicSharedMemorySize,SMB1);
    cudaFuncSetAttribute(gemm_k<2,2,0,1>,cudaFuncAttributeMaxDynamicSharedMemorySize,SMB1);
    float* S; cudaGetSymbolAddress((void**)&S, d_scratch);
    const float* in_g=(const float*)d_in[0];
    const float* in_c=(const float*)d_in[1];
    const float* in_q=(const float*)d_in[2];
    const int* adj_gc=(const int*)d_in[3];
    const int* adj_gq=(const int*)d_in[4];
    const float* aW[3]={(const float*)d_in[5],(const float*)d_in[8],(const float*)d_in[11]};
    const float* aa1[3]={(const float*)d_in[6],(const float*)d_in[9],(const float*)d_in[12]};
    const float* aa2[3]={(const float*)d_in[7],(const float*)d_in[10],(const float*)d_in[13]};
    const float* fus[4]={(const float*)d_in[14],(const float*)d_in[15],(const float*)d_in[16],(const float*)d_in[17]};
    float* out=(float*)d_out;

    unsigned* bgc=(unsigned*)(S+O_BGC);
    unsigned* bgq=(unsigned*)(S+O_BGQ);
    unsigned* bgqT=(unsigned*)(S+O_BGQT);
    __nv_bfloat16* WTH=(__nv_bfloat16*)(S+O_WTH);
    __nv_bfloat16* WTL=(__nv_bfloat16*)(S+O_WTL);
    __nv_bfloat16* FWH=(__nv_bfloat16*)(S+O_FWH);
    __nv_bfloat16* FWL=(__nv_bfloat16*)(S+O_FWL);
    float *gsame=S+O_GS, *agg=S+O_AGG, *G1tmp=S+O_G1;

    bitpack_k<<<512,256>>>(adj_gc,bgc,131072);
    bitpack_k<<<128,256>>>(adj_gq,bgq,32768);
    bitpackT_k<<<128,256>>>(adj_gq,bgqT);
    repack3_k<<<(3*2*HH*FF*DD+255)/256,256>>>(aW[0],aW[1],aW[2],WTH,WTL);
    for(int i=0;i<4;i++)
        wsplit_k<<<8192,256>>>(fus[i],FWH+(size_t)i*2097152,FWL+(size_t)i*2097152,2097152);

    for(int l=0;l<2;l++){
        const float *Gin,*Cin,*Qin; float *Gout,*Cout,*Qout;
        if(l==0){ Gin=in_g; Cin=in_c; Qin=in_q; Gout=S+O_G0; Cout=S+O_C0; Qout=S+O_Q0; }
        else    { Gin=S+O_G0; Cin=S+O_C0; Qin=S+O_Q0;
                  Gout=out; Cout=out+SZ_GF; Qout=out+2*SZ_GF; }
        {
            GP p{}; p.M=NC; p.N=512; p.K1=NG; p.Hdiv=1;
            p.bits=bgc; p.bld=NC/32; p.sBits_b=(long long)NG*(NC/32);
            p.B1=Gin; p.ldb1=512; p.sB_b=(long long)NG*512;
            p.C=gsame; p.ldc=512; p.sC_b=(long long)NC*512;
            gemm_k<1,0,0,1><<<dim3(NC/128,8,NB),256,SMB1>>>(p);
        }
        fusion_go(Cin,gsame,NB*NC, FWH,FWL,(size_t)(l*4+0)*262144, Cout);
        attn_go(S,Gin,NG,Cin,NC, WTH+(size_t)(0*2+l)*262144, WTL+(size_t)(0*2+l)*262144,
                aa1[0]+l*HH*DD, aa2[0]+l*HH*DD, bgc,NC/32,(long long)NG*(NC/32), agg);
        fusion_go(Gin,agg,NB*NG, FWH,FWL,(size_t)(l*4+1)*262144, G1tmp);
        attn_go(S,Qin,NQ,Gin,NG, WTH+(size_t)(1*2+l)*262144, WTL+(size_t)(1*2+l)*262144,
                aa1[1]+l*HH*DD, aa2[1]+l*HH*DD, bgqT,NG/32,(long long)NQ*(NG/32), agg);
        fusion_go(Qin,agg,NB*NQ, FWH,FWL,(size_t)(l*4+2)*262144, Qout);
        attn_go(S,Gin,NG,Qin,NQ, WTH+(size_t)(2*2+l)*262144, WTL+(size_t)(2*2+l)*262144,
                aa1[2]+l*HH*DD, aa2[2]+l*HH*DD, bgq,NQ/32,(long long)NG*(NQ/32), agg);
        fusion_go(G1tmp,agg,NB*NG, FWH,FWL,(size_t)(l*4+3)*262144, Gout);
    }
}

// round 10
// speedup vs baseline: 1.3485x; 1.3485x over previous
#include <cuda_runtime.h>
#include <cuda_bf16.h>
#include <cstdint>

constexpr int NB=4, NG=1024, NC=1024, NQ=256, FF=512, HH=8, DD=64;
constexpr size_t SZ_GF=(size_t)NB*NG*FF, SZ_QF=(size_t)NB*NQ*FF;
constexpr size_t O_G0=0,O_C0=O_G0+SZ_GF,O_Q0=O_C0+SZ_GF,O_G1=O_Q0+SZ_QF,O_GS=O_G1+SZ_GF;
constexpr size_t O_PJQ=O_GS+SZ_GF,O_PJK=O_PJQ+SZ_GF,O_AGG=O_PJK+SZ_GF,O_P1=O_AGG+SZ_GF;
constexpr size_t O_EQ=O_P1+SZ_GF,O_EK=O_EQ+32768,O_Q1=O_EK+32768,O_K1=O_Q1+32768;
constexpr size_t O_Q2=O_K1+32768,O_K2=O_Q2+32768,O_CSC=O_K2+32768,O_PS=O_CSC+32768;
constexpr size_t O_BGC=O_PS+262144,O_BGQ=O_BGC+131072,O_BGQT=O_BGQ+32768;
constexpr size_t O_WTH=O_BGQT+32768,O_WTL=O_WTH+786432;
constexpr size_t O_FWH=O_WTL+786432,O_FWL=O_FWH+4194304;
constexpr size_t S_TOT=O_FWL+4194304;
__device__ float d_scratch[S_TOT];

__global__ void bitpack_k(const int* __restrict__ adj, unsigned* __restrict__ bits, int nwords){
    int w=blockIdx.x*256+threadIdx.x; if(w>=nwords) return;
    const int* p=adj+(size_t)w*32; unsigned v=0;
    #pragma unroll
    for(int i=0;i<32;i++) v|=(p[i]>0?1u:0u)<<i;
    bits[w]=v;
}
__global__ void bitpackT_k(const int* __restrict__ adj, unsigned* __restrict__ bits){
    int idx=blockIdx.x*256+threadIdx.x; if(idx>=NB*NQ*(NG/32)) return;
    int gw=idx&31, q=(idx>>5)&255, b=idx>>13;
    unsigned v=0;
    for(int i=0;i<32;i++) v|=(adj[((size_t)b*NG+gw*32+i)*NQ+q]>0?1u:0u)<<i;
    bits[(size_t)b*NQ*32+(size_t)q*32+gw]=v;
}
__global__ void repack3_k(const float* __restrict__ W0,const float* __restrict__ W1,
                          const float* __restrict__ W2, __nv_bfloat16* __restrict__ hi,
                          __nv_bfloat16* __restrict__ lo){
    int i=blockIdx.x*256+threadIdx.x; if(i>=3*2*HH*FF*DD) return;
    int tp=i>>19, j=i&524287;
    int d=j&63, f=(j>>6)&511, h=(j>>15)&7, l=j>>18;
    const float* W=tp==0?W0:(tp==1?W1:W2);
    float v=W[j];
    size_t o=(size_t)tp*2*FF*512+((size_t)(l*FF+f))*512+h*64+d;
    __nv_bfloat16 hh=__float2bfloat16_rn(v);
    hi[o]=hh; lo[o]=__float2bfloat16_rn(v-__bfloat162float(hh));
}
__global__ void wsplit_k(const float* __restrict__ in, __nv_bfloat16* __restrict__ hi,
                         __nv_bfloat16* __restrict__ lo, int n){
    int i=blockIdx.x*256+threadIdx.x; if(i>=n) return;
    float v=in[i];
    __nv_bfloat16 h=__float2bfloat16_rn(v);
    hi[i]=h; lo[i]=__float2bfloat16_rn(v-__bfloat162float(h));
}
__global__ void dot_a_k(const float* __restrict__ X, const float* __restrict__ a,
                        float* __restrict__ raw, float* __restrict__ e1, float* __restrict__ e2, int N){
    int idx=blockIdx.x*256+threadIdx.x; if(idx>=NB*HH*N) return;
    int n=idx%N, h=(idx/N)%HH, b=idx/(N*HH);
    const float* xp=X+((size_t)(b*N+n))*FF+h*DD; const float* ap=a+h*DD;
    float s=0.f;
    #pragma unroll
    for(int i=0;i<DD;i+=4){
        float4 xv=*(const float4*)(xp+i); float4 av=*(const float4*)(ap+i);
        s+=xv.x*av.x+xv.y*av.y+xv.z*av.z+xv.w*av.w;
    }
    raw[idx]=s; e1[idx]=__expf(s); e2[idx]=__expf(0.2f*s);
}
__global__ void bitsum_k(const unsigned* __restrict__ bits,
    const float* __restrict__ rq,const float* __restrict__ q1,const float* __restrict__ q2,
    const float* __restrict__ rk,const float* __restrict__ k1,const float* __restrict__ k2,
    float* __restrict__ ps, int Nn,int Mm,int bld,int nch,long long sb){
    __shared__ unsigned wb[32][4];
    __shared__ float qt[3][8][32];
    int t=threadIdx.x, m=blockIdx.x*128+t, b=blockIdx.z;
    int nbase=blockIdx.y*256;
    float acc[8]={}; float rkv[8],k1v[8],k2v[8];
    #pragma unroll
    for(int h=0;h<8;h++){ int bh=b*8+h; rkv[h]=rk[(size_t)bh*Mm+m]; k1v[h]=k1[(size_t)bh*Mm+m]; k2v[h]=k2[(size_t)bh*Mm+m]; }
    const unsigned* bb=bits+(size_t)b*sb+blockIdx.x*4;
    for(int n0=nbase;n0<nbase+256;n0+=32){
        wb[t>>2][t&3]=bb[(size_t)(n0+(t>>2))*bld+(t&3)];
        for(int i=t;i<768;i+=128){
            int which=i>>8, r=i&255, h=r>>5, nn=r&31;
            const float* src=which==0?rq:(which==1?q1:q2);
            qt[which][h][nn]=src[(size_t)(b*8+h)*Nn+n0+nn];
        }
        __syncthreads();
        int mw=t>>5, msh=t&31;
        for(int nn=0;nn<32;nn++){
            if((wb[nn][mw]>>msh)&1u){
                #pragma unroll
                for(int h=0;h<8;h++){
                    bool c=qt[0][h][nn]+rkv[h]>0.f;
                    acc[h]+= c? qt[1][h][nn]*k1v[h] : qt[2][h][nn]*k2v[h];
                }
            }
        }
        __syncthreads();
    }
    #pragma unroll
    for(int h=0;h<8;h++) ps[((size_t)(b*8+h)*Mm+m)*nch+blockIdx.y]=acc[h];
}
__global__ void csmerge_k(const float* __restrict__ ps, float* __restrict__ cs, int Mm, int nch){
    int idx=blockIdx.x*256+threadIdx.x; if(idx>=NB*HH*Mm) return;
    float s=0.f;
    for(int c=0;c<nch;c++) s+=ps[(size_t)idx*nch+c];
    cs[idx]=(s>0.f)?(1.f/s):0.f;
}

// ============ bf16-split mma.sync GEMM with ldmatrix ============
struct GP {
    int M,N,K1,K2,Hdiv;
    const float *A1,*B1,*A2;
    int lda1,ldb1,lda2,ldc;
    float* C;
    const float *E1,*E2,*scv;
    const float *qr,*qe1,*qe2,*kr,*ke1,*ke2;
    const __nv_bfloat16 *BH[2],*BL[2];
    long long sA_b,sA_h,sB_b,sB_h,sC_b,sC_h,sSc;
    const unsigned* bits; int bld; long long sBits_b;
};
__device__ __forceinline__ void mma16816(float* c, const unsigned* a, const unsigned* b){
    asm volatile("mma.sync.aligned.m16n8k16.row.col.f32.bf16.bf16.f32 "
        "{%0,%1,%2,%3},{%4,%5,%6,%7},{%8,%9},{%0,%1,%2,%3};"
        : "+f"(c[0]),"+f"(c[1]),"+f"(c[2]),"+f"(c[3])
        : "r"(a[0]),"r"(a[1]),"r"(a[2]),"r"(a[3]),"r"(b[0]),"r"(b[1]));
}
#define LDSM4(d,a) asm volatile("ldmatrix.sync.aligned.m8n8.x4.shared.b16 {%0,%1,%2,%3},[%4];":"=r"((d)[0]),"=r"((d)[1]),"=r"((d)[2]),"=r"((d)[3]):"r"(a))
#define LDSM4T(d,a) asm volatile("ldmatrix.sync.aligned.m8n8.x4.trans.shared.b16 {%0,%1,%2,%3},[%4];":"=r"((d)[0]),"=r"((d)[1]),"=r"((d)[2]),"=r"((d)[3]):"r"(a))
#define SWZA(r,c) (((r)<<5)+((((c)>>3)^(((r)>>1)&3))<<3)+((c)&7))
#define SWZB(r,c) (((r)<<6)+((((c)>>3)^((r)&7))<<3)+((c)&7))
constexpr int A_H=128*32, B_H=32*64;
constexpr int OFF_AL=A_H, OFF_BH=2*A_H, OFF_BL=2*A_H+B_H;
constexpr int SSTR=2*A_H+2*B_H;
constexpr int SMB=2*SSTR*2+3*1024*4;

template<int EPI>
__device__ __forceinline__ void epi_pair(float x0,float x1,float* cp,const float* e1,const float* e2){
    float2 o;
    if(EPI==0){ o.x=x0; o.y=x1; }
    else if(EPI==2){
        o.x=x0>0.f?x0:__expf(x0)-1.f; o.y=x1>0.f?x1:__expf(x1)-1.f;
    } else {
        float2 v1=*(const float2*)e1, v2=*(const float2*)e2; float f;
        f=1.f/(1.f+__expf(-x0)); o.x=v2.x+f*(v1.x-v2.x);
        f=1.f/(1.f+__expf(-x1)); o.y=v2.y+f*(v1.y-v2.y);
    }
    *(float2*)cp=o;
}

template<int ASRC,int EPI,int BPRE>
__global__ void __launch_bounds__(256) gemm_k(GP p){
    extern __shared__ __nv_bfloat16 sm[];
    const int t=threadIdx.x, lane=t&31, wid=t>>5;
    const int wm=wid&3, wn=wid>>2, g=lane>>2, tc=lane&3;
    const int m0=blockIdx.x*128, n0=blockIdx.y*64, z=blockIdx.z;
    const int zb=z/p.Hdiv, zh=z%p.Hdiv;
    const float* B1=p.B1?(p.B1+zb*p.sB_b+zh*p.sB_h):nullptr;
    float* C=p.C+zb*p.sC_b+zh*p.sC_h;
    const float* A1=nullptr; const unsigned* bitsp=nullptr;
    if(ASRC==0) A1=p.A1+zb*p.sA_b+zh*p.sA_h;
    else        bitsp=p.bits+zb*p.sBits_b;
    const float* scv=(ASRC==2)?(p.scv+(long long)z*p.sSc):nullptr;
    const int Ktot=p.K1+p.K2, niter=Ktot>>5;
    float acc[2][4][4]={};
    float rA[16], rB[8]; unsigned rW=0;
    uint4 rBH, rBL;
    const int ar=t>>1, akq=(t&1)*16;
    const int br=t>>3, bnq=(t&7)*8;
    const int wk=t&31, wsel=t>>5;
    float rqv=0.f,q1v=0.f,q2v=0.f;
    float* kt=(float*)(sm+2*SSTR);
    unsigned smb=(unsigned)__cvta_generic_to_shared(sm);
    unsigned aAddr[2][2], bAddr[2][2];
    {
        int rA_=wm*32+(lane&15), cgA=(lane>>4)*8;
        #pragma unroll
        for(int mt=0;mt<2;mt++)
            #pragma unroll
            for(int k2=0;k2<2;k2++) aAddr[mt][k2]=smb+2u*SWZA(rA_+mt*16, cgA+k2*16);
        int rB_=(lane&7)+((lane>>3)&1)*8, cB=wn*32+(lane>>4)*8;
        #pragma unroll
        for(int pp=0;pp<2;pp++)
            #pragma unroll
            for(int k2=0;k2<2;k2++) bAddr[pp][k2]=smb+2u*(OFF_BH+SWZB(rB_+k2*16, cB+pp*16));
    }
    if(ASRC==2){
        long long qo=(long long)z*p.M; int n=m0+ar;
        rqv=p.qr[qo+n]; q1v=p.qe1[qo+n]; q2v=p.qe2[qo+n];
        long long ko=(long long)z*p.K1;
        for(int i=t;i<p.K1;i+=256){
            kt[i]=p.kr[ko+i]; kt[p.K1+i]=p.ke1[ko+i]; kt[2*p.K1+i]=p.ke2[ko+i];
        }
        __syncthreads();
    }

    auto loadregs=[&](int it){
        int kk=it<<5;
        if(ASRC==0){
            const float* Ap; int ldA,ko;
            if(kk<p.K1){Ap=A1; ldA=p.lda1; ko=kk;} else {Ap=p.A2; ldA=p.lda2; ko=kk-p.K1;}
            const float* s=Ap+(long long)(m0+ar)*ldA+ko+akq;
            #pragma unroll
            for(int q=0;q<4;q++) *(float4*)(rA+q*4)=*(const float4*)(s+q*4);
        } else if(ASRC==1){
            rW=bitsp[(long long)(kk+wk)*p.bld+((unsigned)m0>>5)+(wsel>>1)];
        } else {
            rW=bitsp[(size_t)(m0+ar)*p.bld+(kk>>5)];
        }
        if(BPRE){
            int sec=(kk>=p.K1)?1:0, ko=sec?kk-p.K1:kk;
            long long off=(long long)(ko+br)*512+n0+bnq;
            rBH=*(const uint4*)(p.BH[sec]+off);
            rBL=*(const uint4*)(p.BL[sec]+off);
        } else {
            const float* s=B1+(long long)(kk+br)*p.ldb1+n0+bnq;
            *(float4*)(rB)=*(const float4*)(s);
            *(float4*)(rB+4)=*(const float4*)(s+4);
            if(ASRC==2){
                float scl=scv[kk+br];
                #pragma unroll
                for(int i=0;i<8;i++) rB[i]*=scl;
            }
        }
    };
    auto storesm=[&](int buf,int kk){
        __nv_bfloat16* base=sm+buf*SSTR;
        if(ASRC==0){
            #pragma unroll
            for(int i=0;i<16;i+=2){
                float x0=rA[i], x1=rA[i+1];
                __nv_bfloat16 h0=__float2bfloat16_rn(x0), h1=__float2bfloat16_rn(x1);
                __nv_bfloat16 l0=__float2bfloat16_rn(x0-__bfloat162float(h0));
                __nv_bfloat16 l1=__float2bfloat16_rn(x1-__bfloat162float(h1));
                int o=SWZA(ar,akq+i);
                *(__nv_bfloat162*)(base+o)=__nv_bfloat162(h0,h1);
                *(__nv_bfloat162*)(base+OFF_AL+o)=__nv_bfloat162(l0,l1);
            }
        } else if(ASRC==1){
            int mb=wsel*16, sh=(wsel&1)*16;
            #pragma unroll
            for(int i=0;i<16;i++)
                base[SWZA(mb+i,wk)]=__float2bfloat16_rn((float)((rW>>(sh+i))&1u));
        } else {
            #pragma unroll
            for(int i=0;i<16;i++){
                float v=0.f;
                if((rW>>(akq+i))&1u){
                    int mI=kk+akq+i;
                    v=(rqv+kt[mI]>0.f)?(q1v*kt[p.K1+mI]):(q2v*kt[2*p.K1+mI]);
                }
                __nv_bfloat16 h=__float2bfloat16_rn(v);
                int o=SWZA(ar,akq+i);
                base[o]=h; base[OFF_AL+o]=__float2bfloat16_rn(v-__bfloat162float(h));
            }
        }
        int o=SWZB(br,bnq);
        if(BPRE){
            *(uint4*)(base+OFF_BH+o)=rBH;
            *(uint4*)(base+OFF_BL+o)=rBL;
        } else {
            __nv_bfloat162 hp[4], lp[4];
            #pragma unroll
            for(int j=0;j<4;j++){
                float x0=rB[2*j], x1=rB[2*j+1];
                __nv_bfloat16 h0=__float2bfloat16_rn(x0), h1=__float2bfloat16_rn(x1);
                hp[j]=__nv_bfloat162(h0,h1);
                lp[j]=__nv_bfloat162(__float2bfloat16_rn(x0-__bfloat162float(h0)),
                                     __float2bfloat16_rn(x1-__bfloat162float(h1)));
            }
            *(uint4*)(base+OFF_BH+o)=*(uint4*)hp;
            *(uint4*)(base+OFF_BL+o)=*(uint4*)lp;
        }
    };

    loadregs(0);
    for(int it=0;it<niter;it++){
        int buf=it&1;
        storesm(buf,it<<5);
        __syncthreads();
        if(it+1<niter) loadregs(it+1);
        unsigned bo=(unsigned)buf*SSTR*2u;
        #pragma unroll
        for(int k2=0;k2<2;k2++){
            unsigned aH[2][4], aL[2][4], bH[2][4], bL[2][4];
            #pragma unroll
            for(int mt=0;mt<2;mt++){
                LDSM4(aH[mt], aAddr[mt][k2]+bo);
                if(ASRC!=1) LDSM4(aL[mt], aAddr[mt][k2]+bo+2u*OFF_AL);
            }
            #pragma unroll
            for(int pp=0;pp<2;pp++){
                LDSM4T(bH[pp], bAddr[pp][k2]+bo);
                LDSM4T(bL[pp], bAddr[pp][k2]+bo+2u*(OFF_BL-OFF_BH));
            }
            #pragma unroll
            for(int mt=0;mt<2;mt++)
                #pragma unroll
                for(int nt=0;nt<4;nt++){
                    const unsigned* bh=&bH[nt>>1][(nt&1)*2];
                    const unsigned* bl=&bL[nt>>1][(nt&1)*2];
                    mma16816(acc[mt][nt],aH[mt],bh);
                    mma16816(acc[mt][nt],aH[mt],bl);
                    if(ASRC!=1) mma16816(acc[mt][nt],aL[mt],bh);
                }
        }
        __syncthreads();
    }
    #pragma unroll
    for(int mt=0;mt<2;mt++)
        #pragma unroll
        for(int nt=0;nt<4;nt++){
            long long r0=m0+wm*32+mt*16+g;
            int col=n0+wn*32+nt*8+tc*2;
            float* cp0=C+r0*p.ldc+col; float* cp1=C+(r0+8)*p.ldc+col;
            const float *e10=nullptr,*e20=nullptr,*e11=nullptr,*e21=nullptr;
            if(EPI==1){
                e10=p.E1+r0*p.ldc+col; e20=p.E2+r0*p.ldc+col;
                e11=p.E1+(r0+8)*p.ldc+col; e21=p.E2+(r0+8)*p.ldc+col;
            }
            epi_pair<EPI>(acc[mt][nt][0],acc[mt][nt][1],cp0,e10,e20);
            epi_pair<EPI>(acc[mt][nt][2],acc[mt][nt][3],cp1,e11,e21);
        }
}

static void proj_go(const float* X,int rows,const __nv_bfloat16* WH,const __nv_bfloat16* WL,float* out){
    GP p{}; p.M=rows; p.N=512; p.K1=512; p.Hdiv=1;
    p.A1=X; p.lda1=512; p.BH[0]=WH; p.BL[0]=WL; p.C=out; p.ldc=512;
    gemm_k<0,0,1><<<dim3(rows/128,8,1),256,SMB>>>(p);
}
static void fusion_go(const float* a,const float* bm,int rows,
                      const __nv_bfloat16* FWH,const __nv_bfloat16* FWL,size_t woff,
                      float* P1,float* out){
    GP p{}; p.M=rows; p.N=512; p.K1=512; p.K2=512; p.Hdiv=1;
    p.A1=a; p.lda1=512; p.A2=bm; p.lda2=512;
    p.BH[0]=FWH+0*2097152+woff; p.BH[1]=FWH+1*2097152+woff;
    p.BL[0]=FWL+0*2097152+woff; p.BL[1]=FWL+1*2097152+woff;
    p.C=P1; p.ldc=512;
    gemm_k<0,0,1><<<dim3(rows/128,8,1),256,SMB>>>(p);
    p.BH[0]=FWH+2*2097152+woff; p.BH[1]=FWH+3*2097152+woff;
    p.BL[0]=FWL+2*2097152+woff; p.BL[1]=FWL+3*2097152+woff;
    p.C=out; p.E1=P1; p.E2=a;
    gemm_k<0,1,1><<<dim3(rows/128,8,1),256,SMB>>>(p);
}
static void attn_go(float* S,const float* q,int Nqq,const float* kv,int Nkv,
                    const __nv_bfloat16* WH,const __nv_bfloat16* WL,
                    const float* a1,const float* a2,
                    const unsigned* bits,int bld,long long sb,float* agg){
    float *projQ=S+O_PJQ,*projK=S+O_PJK;
    float *rq=S+O_EQ,*rk=S+O_EK,*q1=S+O_Q1,*k1=S+O_K1,*q2=S+O_Q2,*k2=S+O_K2;
    float *cs=S+O_CSC,*ps=S+O_PS;
    proj_go(q,NB*Nqq,WH,WL,projQ);
    proj_go(kv,NB*Nkv,WH,WL,projK);
    dot_a_k<<<(NB*HH*Nqq+255)/256,256>>>(projQ,a1,rq,q1,q2,Nqq);
    dot_a_k<<<(NB*HH*Nkv+255)/256,256>>>(projK,a2,rk,k1,k2,Nkv);
    int nch=Nqq/256;
    bitsum_k<<<dim3(Nkv/128,nch,NB),128>>>(bits,rq,q1,q2,rk,k1,k2,ps,Nqq,Nkv,bld,nch,sb);
    csmerge_k<<<(NB*HH*Nkv+255)/256,256>>>(ps,cs,Nkv,nch);
    GP p{}; p.M=Nqq; p.N=64; p.K1=Nkv; p.Hdiv=HH;
    p.B1=projK; p.ldb1=512; p.sB_b=(long long)Nkv*512; p.sB_h=64;
    p.C=agg; p.ldc=512; p.sC_b=(long long)Nqq*512; p.sC_h=64;
    p.scv=cs; p.sSc=Nkv;
    p.qr=rq; p.qe1=q1; p.qe2=q2; p.kr=rk; p.ke1=k1; p.ke2=k2;
    p.bits=bits; p.bld=bld; p.sBits_b=sb;
    gemm_k<2,2,0><<<dim3(Nqq/128,1,NB*HH),256,SMB>>>(p);
}

extern "C" void kernel_launch(void* const* d_in, const int* in_sizes, int n_in,
                              void* d_out, int out_size){
    cudaFuncSetAttribute(gemm_k<0,0,1>,cudaFuncAttributeMaxDynamicSharedMemorySize,SMB);
    cudaFuncSetAttribute(gemm_k<0,1,1>,cudaFuncAttributeMaxDynamicSharedMemorySize,SMB);
    cudaFuncSetAttribute(gemm_k<1,0,0>,cudaFuncAttributeMaxDynamicSharedMemorySize,SMB);
    cudaFuncSetAttribute(gemm_k<2,2,0>,cudaFuncAttributeMaxDynamicSharedMemorySize,SMB);
    float* S; cudaGetSymbolAddress((void**)&S, d_scratch);
    const float* in_g=(const float*)d_in[0];
    const float* in_c=(const float*)d_in[1];
    const float* in_q=(const float*)d_in[2];
    const int* adj_gc=(const int*)d_in[3];
    const int* adj_gq=(const int*)d_in[4];
    const float* aW[3]={(const float*)d_in[5],(const float*)d_in[8],(const float*)d_in[11]};
    const float* aa1[3]={(const float*)d_in[6],(const float*)d_in[9],(const float*)d_in[12]};
    const float* aa2[3]={(const float*)d_in[7],(const float*)d_in[10],(const float*)d_in[13]};
    const float* fus[4]={(const float*)d_in[14],(const float*)d_in[15],(const float*)d_in[16],(const float*)d_in[17]};
    float* out=(float*)d_out;

    unsigned* bgc=(unsigned*)(S+O_BGC);
    unsigned* bgq=(unsigned*)(S+O_BGQ);
    unsigned* bgqT=(unsigned*)(S+O_BGQT);
    __nv_bfloat16* WTH=(__nv_bfloat16*)(S+O_WTH);
    __nv_bfloat16* WTL=(__nv_bfloat16*)(S+O_WTL);
    __nv_bfloat16* FWH=(__nv_bfloat16*)(S+O_FWH);
    __nv_bfloat16* FWL=(__nv_bfloat16*)(S+O_FWL);
    float *gsame=S+O_GS, *agg=S+O_AGG, *P1=S+O_P1, *G1tmp=S+O_G1;

    bitpack_k<<<512,256>>>(adj_gc,bgc,131072);
    bitpack_k<<<128,256>>>(adj_gq,bgq,32768);
    bitpackT_k<<<128,256>>>(adj_gq,bgqT);
    repack3_k<<<(3*2*HH*FF*DD+255)/256,256>>>(aW[0],aW[1],aW[2],WTH,WTL);
    for(int i=0;i<4;i++)
        wsplit_k<<<8192,256>>>(fus[i],FWH+(size_t)i*2097152,FWL+(size_t)i*2097152,2097152);

    for(int l=0;l<2;l++){
        const float *Gin,*Cin,*Qin; float *Gout,*Cout,*Qout;
        if(l==0){ Gin=in_g; Cin=in_c; Qin=in_q; Gout=S+O_G0; Cout=S+O_C0; Qout=S+O_Q0; }
        else    { Gin=S+O_G0; Cin=S+O_C0; Qin=S+O_Q0;
                  Gout=out; Cout=out+SZ_GF; Qout=out+2*SZ_GF; }
        {
            GP p{}; p.M=NC; p.N=512; p.K1=NG; p.Hdiv=1;
            p.bits=bgc; p.bld=NC/32; p.sBits_b=(long long)NG*(NC/32);
            p.B1=Gin; p.ldb1=512; p.sB_b=(long long)NG*512;
            p.C=gsame; p.ldc=512; p.sC_b=(long long)NC*512;
            gemm_k<1,0,0><<<dim3(NC/128,8,NB),256,SMB>>>(p);
        }
        fusion_go(Cin,gsame,NB*NC, FWH,FWL,(size_t)(l*4+0)*262144, P1,Cout);
        attn_go(S,Gin,NG,Cin,NC, WTH+(size_t)(0*2+l)*262144, WTL+(size_t)(0*2+l)*262144,
                aa1[0]+l*HH*DD, aa2[0]+l*HH*DD, bgc,NC/32,(long long)NG*(NC/32), agg);
        fusion_go(Gin,agg,NB*NG, FWH,FWL,(size_t)(l*4+1)*262144, P1,G1tmp);
        attn_go(S,Qin,NQ,Gin,NG, WTH+(size_t)(1*2+l)*262144, WTL+(size_t)(1*2+l)*262144,
                aa1[1]+l*HH*DD, aa2[1]+l*HH*DD, bgqT,NG/32,(long long)NQ*(NG/32), agg);
        fusion_go(Qin,agg,NB*NQ, FWH,FWL,(size_t)(l*4+2)*262144, P1,Qout);
        attn_go(S,Gin,NG,Qin,NQ, WTH+(size_t)(2*2+l)*262144, WTL+(size_t)(2*2+l)*262144,
                aa1[2]+l*HH*DD, aa2[2]+l*HH*DD, bgq,NQ/32,(long long)NG*(NQ/32), agg);
        fusion_go(G1tmp,agg,NB*NG, FWH,FWL,(size_t)(l*4+3)*262144, P1,Gout);
    }
}

// round 11
// speedup vs baseline: 1.4831x; 1.0998x over previous
#include <cuda_runtime.h>
#include <cuda_bf16.h>
#include <cstdint>

constexpr int NB=4, NG=1024, NC=1024, NQ=256, FF=512, HH=8, DD=64;
constexpr size_t SZ_GF=(size_t)NB*NG*FF, SZ_QF=(size_t)NB*NQ*FF;
constexpr size_t MW=1048576, QW=262144;
constexpr size_t O_G0=0,O_C0=O_G0+SZ_GF,O_Q0=O_C0+SZ_GF,O_G1=O_Q0+SZ_QF,O_GS=O_G1+SZ_GF;
constexpr size_t O_PJQ=O_GS+SZ_GF,O_PJK=O_PJQ+SZ_GF,O_AGG=O_PJK+SZ_GF,O_P1=O_AGG+SZ_GF;
constexpr size_t O_EQ=O_P1+SZ_GF,O_EK=O_EQ+32768,O_Q1=O_EK+32768,O_K1=O_Q1+32768;
constexpr size_t O_Q2=O_K1+32768,O_K2=O_Q2+32768,O_CSC=O_K2+32768,O_PS=O_CSC+32768;
constexpr size_t O_BGC=O_PS+262144,O_BGQ=O_BGC+131072,O_BGQT=O_BGQ+32768;
constexpr size_t O_WTH=O_BGQT+32768,O_WTL=O_WTH+786432;
constexpr size_t O_FWH=O_WTL+786432,O_FWL=O_FWH+4194304;
constexpr size_t B0=O_FWL+4194304;
constexpr size_t O_IGH=B0,O_IGL=O_IGH+MW,O_ICH=O_IGL+MW,O_ICL=O_ICH+MW;
constexpr size_t O_IQH=O_ICL+MW,O_IQL=O_IQH+QW;
constexpr size_t O_G0H=O_IQL+QW,O_G0L=O_G0H+MW,O_C0H=O_G0L+MW,O_C0L=O_C0H+MW;
constexpr size_t O_Q0H=O_C0L+MW,O_Q0L=O_Q0H+QW,O_G1H=O_Q0L+QW,O_G1L=O_G1H+MW;
constexpr size_t O_GSH=O_G1L+MW,O_GSL=O_GSH+MW,O_AGH=O_GSL+MW,O_AGL=O_AGH+MW;
constexpr size_t S_TOT=O_AGL+MW;
__device__ float d_scratch[S_TOT];

typedef __nv_bfloat16 bf;
struct Tens{ const float* f; const bf *h,*l; };

__global__ void bitpack_k(const int* __restrict__ adj, unsigned* __restrict__ bits, int nwords){
    int w=blockIdx.x*256+threadIdx.x; if(w>=nwords) return;
    const int* p=adj+(size_t)w*32; unsigned v=0;
    #pragma unroll
    for(int i=0;i<32;i++) v|=(p[i]>0?1u:0u)<<i;
    bits[w]=v;
}
__global__ void bitpackT_k(const int* __restrict__ adj, unsigned* __restrict__ bits){
    int idx=blockIdx.x*256+threadIdx.x; if(idx>=NB*NQ*(NG/32)) return;
    int gw=idx&31, q=(idx>>5)&255, b=idx>>13;
    unsigned v=0;
    for(int i=0;i<32;i++) v|=(adj[((size_t)b*NG+gw*32+i)*NQ+q]>0?1u:0u)<<i;
    bits[(size_t)b*NQ*32+(size_t)q*32+gw]=v;
}
__global__ void repack3_k(const float* __restrict__ W0,const float* __restrict__ W1,
                          const float* __restrict__ W2, bf* __restrict__ hi, bf* __restrict__ lo){
    int i=blockIdx.x*256+threadIdx.x; if(i>=3*2*HH*FF*DD) return;
    int tp=i>>19, j=i&524287;
    int d=j&63, f=(j>>6)&511, h=(j>>15)&7, l=j>>18;
    const float* W=tp==0?W0:(tp==1?W1:W2);
    float v=W[j];
    size_t o=(size_t)tp*2*FF*512+((size_t)(l*FF+f))*512+h*64+d;
    bf hh=__float2bfloat16_rn(v);
    hi[o]=hh; lo[o]=__float2bfloat16_rn(v-__bfloat162float(hh));
}
struct WS{ const float* src[7]; bf *h[7],*l[7]; int n[7]; };
__global__ void wsplit_all(WS w){
    int s=blockIdx.y;
    int i=blockIdx.x*256+threadIdx.x; if(i>=w.n[s]) return;
    float v=w.src[s][i];
    bf h=__float2bfloat16_rn(v);
    w.h[s][i]=h; w.l[s][i]=__float2bfloat16_rn(v-__bfloat162float(h));
}
__global__ void dot_a_k(const float* __restrict__ X, const float* __restrict__ a,
                        float* __restrict__ raw, float* __restrict__ e1, float* __restrict__ e2, int N){
    int idx=blockIdx.x*256+threadIdx.x; if(idx>=NB*HH*N) return;
    int n=idx%N, h=(idx/N)%HH, b=idx/(N*HH);
    const float* xp=X+((size_t)(b*N+n))*FF+h*DD; const float* ap=a+h*DD;
    float s=0.f;
    #pragma unroll
    for(int i=0;i<DD;i+=4){
        float4 xv=*(const float4*)(xp+i); float4 av=*(const float4*)(ap+i);
        s+=xv.x*av.x+xv.y*av.y+xv.z*av.z+xv.w*av.w;
    }
    raw[idx]=s; e1[idx]=__expf(s); e2[idx]=__expf(0.2f*s);
}
__global__ void bitsum_k(const unsigned* __restrict__ bits,
    const float* __restrict__ rq,const float* __restrict__ q1,const float* __restrict__ q2,
    const float* __restrict__ rk,const float* __restrict__ k1,const float* __restrict__ k2,
    float* __restrict__ ps, int Nn,int Mm,int bld,int nch,long long sb){
    __shared__ unsigned wb[32][4];
    __shared__ float qt[3][8][32];
    int t=threadIdx.x, m=blockIdx.x*128+t, b=blockIdx.z;
    int nbase=blockIdx.y*256;
    float acc[8]={}; float rkv[8],k1v[8],k2v[8];
    #pragma unroll
    for(int h=0;h<8;h++){ int bh=b*8+h; rkv[h]=rk[(size_t)bh*Mm+m]; k1v[h]=k1[(size_t)bh*Mm+m]; k2v[h]=k2[(size_t)bh*Mm+m]; }
    const unsigned* bb=bits+(size_t)b*sb+blockIdx.x*4;
    for(int n0=nbase;n0<nbase+256;n0+=32){
        wb[t>>2][t&3]=bb[(size_t)(n0+(t>>2))*bld+(t&3)];
        for(int i=t;i<768;i+=128){
            int which=i>>8, r=i&255, h=r>>5, nn=r&31;
            const float* src=which==0?rq:(which==1?q1:q2);
            qt[which][h][nn]=src[(size_t)(b*8+h)*Nn+n0+nn];
        }
        __syncthreads();
        int mw=t>>5, msh=t&31;
        for(int nn=0;nn<32;nn++){
            if((wb[nn][mw]>>msh)&1u){
                #pragma unroll
                for(int h=0;h<8;h++){
                    bool c=qt[0][h][nn]+rkv[h]>0.f;
                    acc[h]+= c? qt[1][h][nn]*k1v[h] : qt[2][h][nn]*k2v[h];
                }
            }
        }
        __syncthreads();
    }
    #pragma unroll
    for(int h=0;h<8;h++) ps[((size_t)(b*8+h)*Mm+m)*nch+blockIdx.y]=acc[h];
}
__global__ void csmerge_k(const float* __restrict__ ps, float* __restrict__ cs, int Mm, int nch){
    int idx=blockIdx.x*256+threadIdx.x; if(idx>=NB*HH*Mm) return;
    float s=0.f;
    for(int c=0;c<nch;c++) s+=ps[(size_t)idx*nch+c];
    cs[idx]=(s>0.f)?(1.f/s):0.f;
}

// ============ bf16-split mma.sync GEMM, all-pre-split operands ============
struct GP {
    int M,N,K1,K2,Hdiv;
    const bf *A1H,*A1L,*A2H,*A2L;
    const float *B1; int ldb1, ldc;
    const bf *BH[2],*BL[2];
    float* C; bf *CH,*CL;
    const float *E1,*E2,*scv;
    const float *qr,*qe1,*qe2,*kr,*ke1,*ke2;
    long long sB_b,sB_h,sC_b,sC_h,sSc;
    const unsigned* bits; int bld; long long sBits_b;
};
__device__ __forceinline__ void mma16816(float* c, const unsigned* a, const unsigned* b){
    asm volatile("mma.sync.aligned.m16n8k16.row.col.f32.bf16.bf16.f32 "
        "{%0,%1,%2,%3},{%4,%5,%6,%7},{%8,%9},{%0,%1,%2,%3};"
        : "+f"(c[0]),"+f"(c[1]),"+f"(c[2]),"+f"(c[3])
        : "r"(a[0]),"r"(a[1]),"r"(a[2]),"r"(a[3]),"r"(b[0]),"r"(b[1]));
}
#define LDSM4(d,a) asm volatile("ldmatrix.sync.aligned.m8n8.x4.shared.b16 {%0,%1,%2,%3},[%4];":"=r"((d)[0]),"=r"((d)[1]),"=r"((d)[2]),"=r"((d)[3]):"r"(a))
#define LDSM4T(d,a) asm volatile("ldmatrix.sync.aligned.m8n8.x4.trans.shared.b16 {%0,%1,%2,%3},[%4];":"=r"((d)[0]),"=r"((d)[1]),"=r"((d)[2]),"=r"((d)[3]):"r"(a))
#define SWZA(r,c) (((r)<<5)+((((c)>>3)^(((r)>>1)&3))<<3)+((c)&7))
#define SWZB(r,c) (((r)<<6)+((((c)>>3)^((r)&7))<<3)+((c)&7))
constexpr int A_H=128*32, B_H=32*64;
constexpr int OFF_AL=A_H, OFF_BH=2*A_H, OFF_BL=2*A_H+B_H;
constexpr int SSTR=2*A_H+2*B_H;
constexpr int SMB=2*SSTR*2+3*1024*4;

template<int ASRC,int EPI,int BPRE>
__global__ void __launch_bounds__(256) gemm_k(GP p){
    extern __shared__ bf sm[];
    const int t=threadIdx.x, lane=t&31, wid=t>>5;
    const int wm=wid&3, wn=wid>>2, g=lane>>2, tc=lane&3;
    const int m0=blockIdx.x*128, n0=blockIdx.y*64, z=blockIdx.z;
    const int zb=z/p.Hdiv, zh=z-zb*p.Hdiv;
    const float* B1=p.B1?(p.B1+zb*p.sB_b+zh*p.sB_h):nullptr;
    float* C=p.C+zb*p.sC_b+zh*p.sC_h;
    bf* CHp=p.CH?(p.CH+zb*p.sC_b+zh*p.sC_h):nullptr;
    bf* CLp=p.CL?(p.CL+zb*p.sC_b+zh*p.sC_h):nullptr;
    const unsigned* bitsp=nullptr;
    if(ASRC!=0) bitsp=p.bits+zb*p.sBits_b;
    const bf *bhB[2]={nullptr,nullptr},*blB[2]={nullptr,nullptr};
    if(BPRE){
        bhB[0]=p.BH[0]+zb*p.sB_b; blB[0]=p.BL[0]+zb*p.sB_b;
        if(p.BH[1]){ bhB[1]=p.BH[1]+zb*p.sB_b; blB[1]=p.BL[1]+zb*p.sB_b; }
    }
    const float* scv=(ASRC==2)?(p.scv+(long long)z*p.sSc):nullptr;
    const int Ktot=p.K1+p.K2, niter=Ktot>>5;
    float acc[2][4][4]={};
    uint4 rAH[2],rAL[2],rBH,rBL; float rB[8]; unsigned rW=0;
    const int ar=t>>1, akq=(t&1)*16;
    const int br=t>>3, bnq=(t&7)*8;
    const int wk=t&31, wsel=t>>5;
    float rqv=0.f,q1v=0.f,q2v=0.f;
    float* kt=(float*)(sm+2*SSTR);
    unsigned smb=(unsigned)__cvta_generic_to_shared(sm);
    unsigned aAddr[2][2], bAddr[2][2];
    {
        int rA_=wm*32+(lane&15), cgA=(lane>>4)*8;
        #pragma unroll
        for(int mt=0;mt<2;mt++)
            #pragma unroll
            for(int k2=0;k2<2;k2++) aAddr[mt][k2]=smb+2u*SWZA(rA_+mt*16, cgA+k2*16);
        int rB_=(lane&7)+((lane>>3)&1)*8, cB=wn*32+(lane>>4)*8;
        #pragma unroll
        for(int pp=0;pp<2;pp++)
            #pragma unroll
            for(int k2=0;k2<2;k2++) bAddr[pp][k2]=smb+2u*(OFF_BH+SWZB(rB_+k2*16, cB+pp*16));
    }
    if(ASRC==2){
        long long qo=(long long)z*p.M; int n=m0+ar;
        rqv=p.qr[qo+n]; q1v=p.qe1[qo+n]; q2v=p.qe2[qo+n];
        long long ko=(long long)z*p.K1;
        for(int i=t;i<p.K1;i+=256){
            kt[i]=p.kr[ko+i]; kt[p.K1+i]=p.ke1[ko+i]; kt[2*p.K1+i]=p.ke2[ko+i];
        }
        __syncthreads();
    }

    auto loadregs=[&](int it){
        int kk=it<<5;
        if(ASRC==0){
            const bf *ah,*al; int ko;
            if(kk<p.K1){ah=p.A1H; al=p.A1L; ko=kk;} else {ah=p.A2H; al=p.A2L; ko=kk-p.K1;}
            long long off=(long long)(m0+ar)*512+ko+akq;
            rAH[0]=*(const uint4*)(ah+off); rAH[1]=*(const uint4*)(ah+off+8);
            rAL[0]=*(const uint4*)(al+off); rAL[1]=*(const uint4*)(al+off+8);
        } else if(ASRC==1){
            rW=bitsp[(long long)(kk+wk)*p.bld+((unsigned)m0>>5)+(wsel>>1)];
        } else {
            rW=bitsp[(size_t)(m0+ar)*p.bld+(kk>>5)];
        }
        if(BPRE){
            int sec=(kk>=p.K1)?1:0, ko=sec?kk-p.K1:kk;
            long long off=(long long)(ko+br)*512+n0+bnq;
            rBH=*(const uint4*)(bhB[sec]+off);
            rBL=*(const uint4*)(blB[sec]+off);
        } else {
            const float* s=B1+(long long)(kk+br)*p.ldb1+n0+bnq;
            *(float4*)(rB)=*(const float4*)(s);
            *(float4*)(rB+4)=*(const float4*)(s+4);
            if(ASRC==2){
                float scl=scv[kk+br];
                #pragma unroll
                for(int i=0;i<8;i++) rB[i]*=scl;
            }
        }
    };
    auto storesm=[&](int buf,int kk){
        bf* base=sm+buf*SSTR;
        if(ASRC==0){
            int o0=SWZA(ar,akq), o1=SWZA(ar,akq+8);
            *(uint4*)(base+o0)=rAH[0]; *(uint4*)(base+o1)=rAH[1];
            *(uint4*)(base+OFF_AL+o0)=rAL[0]; *(uint4*)(base+OFF_AL+o1)=rAL[1];
        } else if(ASRC==1){
            int mb=wsel*16, sh=(wsel&1)*16;
            #pragma unroll
            for(int i=0;i<16;i++)
                base[SWZA(mb+i,wk)]=__float2bfloat16_rn((float)((rW>>(sh+i))&1u));
        } else {
            #pragma unroll
            for(int i=0;i<16;i++){
                float v=0.f;
                if((rW>>(akq+i))&1u){
                    int mI=kk+akq+i;
                    v=(rqv+kt[mI]>0.f)?(q1v*kt[p.K1+mI]):(q2v*kt[2*p.K1+mI]);
                }
                bf h=__float2bfloat16_rn(v);
                int o=SWZA(ar,akq+i);
                base[o]=h; base[OFF_AL+o]=__float2bfloat16_rn(v-__bfloat162float(h));
            }
        }
        int o=SWZB(br,bnq);
        if(BPRE){
            *(uint4*)(base+OFF_BH+o)=rBH;
            *(uint4*)(base+OFF_BL+o)=rBL;
        } else {
            __nv_bfloat162 hp[4], lp[4];
            #pragma unroll
            for(int j=0;j<4;j++){
                float x0=rB[2*j], x1=rB[2*j+1];
                bf h0=__float2bfloat16_rn(x0), h1=__float2bfloat16_rn(x1);
                hp[j]=__nv_bfloat162(h0,h1);
                lp[j]=__nv_bfloat162(__float2bfloat16_rn(x0-__bfloat162float(h0)),
                                     __float2bfloat16_rn(x1-__bfloat162float(h1)));
            }
            *(uint4*)(base+OFF_BH+o)=*(uint4*)hp;
            *(uint4*)(base+OFF_BL+o)=*(uint4*)lp;
        }
    };

    loadregs(0);
    for(int it=0;it<niter;it++){
        int buf=it&1;
        storesm(buf,it<<5);
        __syncthreads();
        if(it+1<niter) loadregs(it+1);
        unsigned bo=(unsigned)buf*SSTR*2u;
        #pragma unroll
        for(int k2=0;k2<2;k2++){
            unsigned aH[2][4], aL[2][4], bH[2][4], bL[2][4];
            #pragma unroll
            for(int mt=0;mt<2;mt++){
                LDSM4(aH[mt], aAddr[mt][k2]+bo);
                if(ASRC!=1) LDSM4(aL[mt], aAddr[mt][k2]+bo+2u*OFF_AL);
            }
            #pragma unroll
            for(int pp=0;pp<2;pp++){
                LDSM4T(bH[pp], bAddr[pp][k2]+bo);
                LDSM4T(bL[pp], bAddr[pp][k2]+bo+2u*(OFF_BL-OFF_BH));
            }
            #pragma unroll
            for(int mt=0;mt<2;mt++)
                #pragma unroll
                for(int nt=0;nt<4;nt++){
                    const unsigned* bh=&bH[nt>>1][(nt&1)*2];
                    const unsigned* bl=&bL[nt>>1][(nt&1)*2];
                    mma16816(acc[mt][nt],aH[mt],bh);
                    mma16816(acc[mt][nt],aH[mt],bl);
                    if(ASRC!=1) mma16816(acc[mt][nt],aL[mt],bh);
                }
        }
        __syncthreads();
    }
    #pragma unroll
    for(int mt=0;mt<2;mt++)
        #pragma unroll
        for(int nt=0;nt<4;nt++)
            #pragma unroll
            for(int hrow=0;hrow<2;hrow++){
                long long r=m0+wm*32+mt*16+g+hrow*8;
                int col=n0+wn*32+nt*8+tc*2;
                float x0=acc[mt][nt][hrow*2], x1=acc[mt][nt][hrow*2+1];
                float2 o;
                if(EPI==1){
                    float2 v1=*(const float2*)(p.E1+r*p.ldc+col);
                    float2 v2=*(const float2*)(p.E2+r*p.ldc+col);
                    float f0=1.f/(1.f+__expf(-x0)), f1=1.f/(1.f+__expf(-x1));
                    o.x=v2.x+f0*(v1.x-v2.x); o.y=v2.y+f1*(v1.y-v2.y);
                } else if(EPI==2){
                    o.x=x0>0.f?x0:__expf(x0)-1.f; o.y=x1>0.f?x1:__expf(x1)-1.f;
                } else { o.x=x0; o.y=x1; }
                *(float2*)(C+r*p.ldc+col)=o;
                if(CHp){
                    bf h0=__float2bfloat16_rn(o.x), h1=__float2bfloat16_rn(o.y);
                    *(__nv_bfloat162*)(CHp+r*p.ldc+col)=__nv_bfloat162(h0,h1);
                    *(__nv_bfloat162*)(CLp+r*p.ldc+col)=__nv_bfloat162(
                        __float2bfloat16_rn(o.x-__bfloat162float(h0)),
                        __float2bfloat16_rn(o.y-__bfloat162float(h1)));
                }
            }
}

static void proj_go(Tens X,int rows,const bf* WH,const bf* WL,float* out){
    GP p{}; p.M=rows; p.N=512; p.K1=512; p.Hdiv=1;
    p.A1H=X.h; p.A1L=X.l; p.BH[0]=WH; p.BL[0]=WL; p.C=out; p.ldc=512;
    gemm_k<0,0,1><<<dim3(rows/128,8,1),256,SMB>>>(p);
}
static void fusion_go(Tens a,Tens bm,int rows,
                      const bf* FWH,const bf* FWL,size_t woff,
                      float* P1,float* out,bf* outH,bf* outL){
    GP p{}; p.M=rows; p.N=512; p.K1=512; p.K2=512; p.Hdiv=1;
    p.A1H=a.h; p.A1L=a.l; p.A2H=bm.h; p.A2L=bm.l;
    p.BH[0]=FWH+0*2097152+woff; p.BH[1]=FWH+1*2097152+woff;
    p.BL[0]=FWL+0*2097152+woff; p.BL[1]=FWL+1*2097152+woff;
    p.C=P1; p.ldc=512;
    gemm_k<0,0,1><<<dim3(rows/128,8,1),256,SMB>>>(p);
    p.BH[0]=FWH+2*2097152+woff; p.BH[1]=FWH+3*2097152+woff;
    p.BL[0]=FWL+2*2097152+woff; p.BL[1]=FWL+3*2097152+woff;
    p.C=out; p.CH=outH; p.CL=outL; p.E1=P1; p.E2=a.f;
    gemm_k<0,1,1><<<dim3(rows/128,8,1),256,SMB>>>(p);
}
static void attn_go(float* S,Tens q,int Nqq,Tens kv,int Nkv,
                    const bf* WH,const bf* WL,const float* a1,const float* a2,
                    const unsigned* bits,int bld,long long sb,
                    float* agg,bf* aggH,bf* aggL){
    float *projQ=S+O_PJQ,*projK=S+O_PJK;
    float *rq=S+O_EQ,*rk=S+O_EK,*q1=S+O_Q1,*k1=S+O_K1,*q2=S+O_Q2,*k2=S+O_K2;
    float *cs=S+O_CSC,*ps=S+O_PS;
    proj_go(q,NB*Nqq,WH,WL,projQ);
    proj_go(kv,NB*Nkv,WH,WL,projK);
    dot_a_k<<<(NB*HH*Nqq+255)/256,256>>>(projQ,a1,rq,q1,q2,Nqq);
    dot_a_k<<<(NB*HH*Nkv+255)/256,256>>>(projK,a2,rk,k1,k2,Nkv);
    int nch=Nqq/256;
    bitsum_k<<<dim3(Nkv/128,nch,NB),128>>>(bits,rq,q1,q2,rk,k1,k2,ps,Nqq,Nkv,bld,nch,sb);
    csmerge_k<<<(NB*HH*Nkv+255)/256,256>>>(ps,cs,Nkv,nch);
    GP p{}; p.M=Nqq; p.N=64; p.K1=Nkv; p.Hdiv=HH;
    p.B1=projK; p.ldb1=512; p.sB_b=(long long)Nkv*512; p.sB_h=64;
    p.C=agg; p.ldc=512; p.sC_b=(long long)Nqq*512; p.sC_h=64;
    p.CH=aggH; p.CL=aggL;
    p.scv=cs; p.sSc=Nkv;
    p.qr=rq; p.qe1=q1; p.qe2=q2; p.kr=rk; p.ke1=k1; p.ke2=k2;
    p.bits=bits; p.bld=bld; p.sBits_b=sb;
    gemm_k<2,2,0><<<dim3(Nqq/128,1,NB*HH),256,SMB>>>(p);
}

extern "C" void kernel_launch(void* const* d_in, const int* in_sizes, int n_in,
                              void* d_out, int out_size){
    cudaFuncSetAttribute(gemm_k<0,0,1>,cudaFuncAttributeMaxDynamicSharedMemorySize,SMB);
    cudaFuncSetAttribute(gemm_k<0,1,1>,cudaFuncAttributeMaxDynamicSharedMemorySize,SMB);
    cudaFuncSetAttribute(gemm_k<1,0,1>,cudaFuncAttributeMaxDynamicSharedMemorySize,SMB);
    cudaFuncSetAttribute(gemm_k<2,2,0>,cudaFuncAttributeMaxDynamicSharedMemorySize,SMB);
    float* S; cudaGetSymbolAddress((void**)&S, d_scratch);
    const float* in_g=(const float*)d_in[0];
    const float* in_c=(const float*)d_in[1];
    const float* in_q=(const float*)d_in[2];
    const int* adj_gc=(const int*)d_in[3];
    const int* adj_gq=(const int*)d_in[4];
    const float* aW[3]={(const float*)d_in[5],(const float*)d_in[8],(const float*)d_in[11]};
    const float* aa1[3]={(const float*)d_in[6],(const float*)d_in[9],(const float*)d_in[12]};
    const float* aa2[3]={(const float*)d_in[7],(const float*)d_in[10],(const float*)d_in[13]};
    const float* fus[4]={(const float*)d_in[14],(const float*)d_in[15],(const float*)d_in[16],(const float*)d_in[17]};
    float* out=(float*)d_out;

    unsigned* bgc=(unsigned*)(S+O_BGC);
    unsigned* bgq=(unsigned*)(S+O_BGQ);
    unsigned* bgqT=(unsigned*)(S+O_BGQT);
    bf* WTH=(bf*)(S+O_WTH); bf* WTL=(bf*)(S+O_WTL);
    bf* FWH=(bf*)(S+O_FWH); bf* FWL=(bf*)(S+O_FWL);
    #define BFP(o) ((bf*)(S+(o)))
    float *gsame=S+O_GS, *agg=S+O_AGG, *P1=S+O_P1, *G1f=S+O_G1;

    bitpack_k<<<512,256>>>(adj_gc,bgc,131072);
    bitpack_k<<<128,256>>>(adj_gq,bgq,32768);
    bitpackT_k<<<128,256>>>(adj_gq,bgqT);
    repack3_k<<<(3*2*HH*FF*DD+255)/256,256>>>(aW[0],aW[1],aW[2],WTH,WTL);
    {
        WS w{};
        for(int i=0;i<4;i++){ w.src[i]=fus[i]; w.h[i]=FWH+(size_t)i*2097152; w.l[i]=FWL+(size_t)i*2097152; w.n[i]=2097152; }
        w.src[4]=in_g; w.h[4]=BFP(O_IGH); w.l[4]=BFP(O_IGL); w.n[4]=2097152;
        w.src[5]=in_c; w.h[5]=BFP(O_ICH); w.l[5]=BFP(O_ICL); w.n[5]=2097152;
        w.src[6]=in_q; w.h[6]=BFP(O_IQH); w.l[6]=BFP(O_IQL); w.n[6]=524288;
        wsplit_all<<<dim3(8192,7),256>>>(w);
    }

    Tens GS={gsame,BFP(O_GSH),BFP(O_GSL)};
    Tens AG={agg,BFP(O_AGH),BFP(O_AGL)};
    Tens G1={G1f,BFP(O_G1H),BFP(O_G1L)};

    for(int l=0;l<2;l++){
        Tens G,C,Q; float *Gout,*Cout,*Qout; bf *GoH,*GoL,*CoH,*CoL,*QoH,*QoL;
        if(l==0){
            G={in_g,BFP(O_IGH),BFP(O_IGL)}; C={in_c,BFP(O_ICH),BFP(O_ICL)}; Q={in_q,BFP(O_IQH),BFP(O_IQL)};
            Gout=S+O_G0; Cout=S+O_C0; Qout=S+O_Q0;
            GoH=BFP(O_G0H); GoL=BFP(O_G0L); CoH=BFP(O_C0H); CoL=BFP(O_C0L); QoH=BFP(O_Q0H); QoL=BFP(O_Q0L);
        } else {
            G={S+O_G0,BFP(O_G0H),BFP(O_G0L)}; C={S+O_C0,BFP(O_C0H),BFP(O_C0L)}; Q={S+O_Q0,BFP(O_Q0H),BFP(O_Q0L)};
            Gout=out; Cout=out+SZ_GF; Qout=out+2*SZ_GF;
            GoH=GoL=CoH=CoL=QoH=QoL=nullptr;
        }
        // 1) gloss_same = adj^T @ gloss : A from bits, B = G pre-split
        {
            GP p{}; p.M=NC; p.N=512; p.K1=NG; p.Hdiv=1;
            p.bits=bgc; p.bld=NC/32; p.sBits_b=(long long)NG*(NC/32);
            p.BH[0]=G.h; p.BL[0]=G.l; p.sB_b=(long long)NG*512;
            p.C=gsame; p.ldc=512; p.sC_b=(long long)NC*512;
            p.CH=(bf*)GS.h; p.CL=(bf*)GS.l;
            gemm_k<1,0,1><<<dim3(NC/128,8,NB),256,SMB>>>(p);
        }
        fusion_go(C,GS,NB*NC, FWH,FWL,(size_t)(l*4+0)*262144, P1,Cout,CoH,CoL);
        attn_go(S,G,NG,C,NC, WTH+(size_t)(0*2+l)*262144, WTL+(size_t)(0*2+l)*262144,
                aa1[0]+l*HH*DD, aa2[0]+l*HH*DD, bgc,NC/32,(long long)NG*(NC/32),
                agg,(bf*)AG.h,(bf*)AG.l);
        fusion_go(G,AG,NB*NG, FWH,FWL,(size_t)(l*4+1)*262144, P1,G1f,(bf*)G1.h,(bf*)G1.l);
        attn_go(S,Q,NQ,G,NG, WTH+(size_t)(1*2+l)*262144, WTL+(size_t)(1*2+l)*262144,
                aa1[1]+l*HH*DD, aa2[1]+l*HH*DD, bgqT,NG/32,(long long)NQ*(NG/32),
                agg,(bf*)AG.h,(bf*)AG.l);
        fusion_go(Q,AG,NB*NQ, FWH,FWL,(size_t)(l*4+2)*262144, P1,Qout,QoH,QoL);
        attn_go(S,G,NG,Q,NQ, WTH+(size_t)(2*2+l)*262144, WTL+(size_t)(2*2+l)*262144,
                aa1[2]+l*HH*DD, aa2[2]+l*HH*DD, bgq,NQ/32,(long long)NG*(NQ/32),
                agg,(bf*)AG.h,(bf*)AG.l);
        fusion_go(G1,AG,NB*NG, FWH,FWL,(size_t)(l*4+3)*262144, P1,Gout,GoH,GoL);
    }
}

// round 12
// speedup vs baseline: 1.5151x; 1.0216x over previous
#include <cuda_runtime.h>
#include <cuda_bf16.h>
#include <cstdint>

constexpr int NB=4, NG=1024, NC=1024, NQ=256, FF=512, HH=8, DD=64;
constexpr size_t SZ_GF=(size_t)NB*NG*FF, SZ_QF=(size_t)NB*NQ*FF;
constexpr size_t MW=1048576, QW=262144;
constexpr size_t O_G0=0,O_C0=O_G0+SZ_GF,O_Q0=O_C0+SZ_GF,O_G1=O_Q0+SZ_QF,O_GS=O_G1+SZ_GF;
constexpr size_t O_PJQ=O_GS+SZ_GF,O_PJK=O_PJQ+SZ_GF,O_AGG=O_PJK+SZ_GF,O_P1=O_AGG+SZ_GF;
constexpr size_t O_EQ=O_P1+SZ_GF,O_EK=O_EQ+32768,O_Q1=O_EK+32768,O_K1=O_Q1+32768;
constexpr size_t O_Q2=O_K1+32768,O_K2=O_Q2+32768,O_CSC=O_K2+32768,O_PS=O_CSC+32768;
constexpr size_t O_BGC=O_PS+262144,O_BGQ=O_BGC+131072,O_BGQT=O_BGQ+32768;
constexpr size_t O_WTH=O_BGQT+32768,O_WTL=O_WTH+786432;
constexpr size_t O_FWH=O_WTL+786432,O_FWL=O_FWH+4194304;
constexpr size_t B0=O_FWL+4194304;
constexpr size_t O_IGH=B0,O_IGL=O_IGH+MW,O_ICH=O_IGL+MW,O_ICL=O_ICH+MW;
constexpr size_t O_IQH=O_ICL+MW,O_IQL=O_IQH+QW;
constexpr size_t O_G0H=O_IQL+QW,O_G0L=O_G0H+MW,O_C0H=O_G0L+MW,O_C0L=O_C0H+MW;
constexpr size_t O_Q0H=O_C0L+MW,O_Q0L=O_Q0H+QW,O_G1H=O_Q0L+QW,O_G1L=O_G1H+MW;
constexpr size_t O_GSH=O_G1L+MW,O_GSL=O_GSH+MW,O_AGH=O_GSL+MW,O_AGL=O_AGH+MW;
constexpr size_t S_TOT=O_AGL+MW;
__device__ float d_scratch[S_TOT];

typedef __nv_bfloat16 bf;
struct Tens{ const float* f; const bf *h,*l; };

__global__ void bitpack_k(const int* __restrict__ adj, unsigned* __restrict__ bits, int nwords){
    int w=blockIdx.x*256+threadIdx.x; if(w>=nwords) return;
    const int* p=adj+(size_t)w*32; unsigned v=0;
    #pragma unroll
    for(int i=0;i<32;i++) v|=(p[i]>0?1u:0u)<<i;
    bits[w]=v;
}
__global__ void bitpackT_k(const int* __restrict__ adj, unsigned* __restrict__ bits){
    int idx=blockIdx.x*256+threadIdx.x; if(idx>=NB*NQ*(NG/32)) return;
    int gw=idx&31, q=(idx>>5)&255, b=idx>>13;
    unsigned v=0;
    for(int i=0;i<32;i++) v|=(adj[((size_t)b*NG+gw*32+i)*NQ+q]>0?1u:0u)<<i;
    bits[(size_t)b*NQ*32+(size_t)q*32+gw]=v;
}
__global__ void repack3_k(const float* __restrict__ W0,const float* __restrict__ W1,
                          const float* __restrict__ W2, bf* __restrict__ hi, bf* __restrict__ lo){
    int i=blockIdx.x*256+threadIdx.x; if(i>=3*2*HH*FF*DD) return;
    int tp=i>>19, j=i&524287;
    int d=j&63, f=(j>>6)&511, h=(j>>15)&7, l=j>>18;
    const float* W=tp==0?W0:(tp==1?W1:W2);
    float v=W[j];
    size_t o=(size_t)tp*2*FF*512+((size_t)(l*FF+f))*512+h*64+d;
    bf hh=__float2bfloat16_rn(v);
    hi[o]=hh; lo[o]=__float2bfloat16_rn(v-__bfloat162float(hh));
}
struct WS{ const float* src[7]; bf *h[7],*l[7]; int n[7]; };
__global__ void wsplit_all(WS w){
    int s=blockIdx.y;
    int i=blockIdx.x*256+threadIdx.x; if(i>=w.n[s]) return;
    float v=w.src[s][i];
    bf h=__float2bfloat16_rn(v);
    w.h[s][i]=h; w.l[s][i]=__float2bfloat16_rn(v-__bfloat162float(h));
}
__global__ void dot_a_k(const float* __restrict__ X, const float* __restrict__ a,
                        float* __restrict__ raw, float* __restrict__ e1, float* __restrict__ e2, int N){
    int idx=blockIdx.x*256+threadIdx.x; if(idx>=NB*HH*N) return;
    int n=idx%N, h=(idx/N)%HH, b=idx/(N*HH);
    const float* xp=X+((size_t)(b*N+n))*FF+h*DD; const float* ap=a+h*DD;
    float s=0.f;
    #pragma unroll
    for(int i=0;i<DD;i+=4){
        float4 xv=*(const float4*)(xp+i); float4 av=*(const float4*)(ap+i);
        s+=xv.x*av.x+xv.y*av.y+xv.z*av.z+xv.w*av.w;
    }
    raw[idx]=s; e1[idx]=__expf(s); e2[idx]=__expf(0.2f*s);
}
__global__ void bitsum_k(const unsigned* __restrict__ bits,
    const float* __restrict__ rq,const float* __restrict__ q1,const float* __restrict__ q2,
    const float* __restrict__ rk,const float* __restrict__ k1,const float* __restrict__ k2,
    float* __restrict__ ps, int Nn,int Mm,int bld,int nch,long long sb){
    __shared__ unsigned wb[32][4];
    __shared__ float qt[3][8][32];
    int t=threadIdx.x, m=blockIdx.x*128+t, b=blockIdx.z;
    int nbase=blockIdx.y*256;
    float acc[8]={}; float rkv[8],k1v[8],k2v[8];
    #pragma unroll
    for(int h=0;h<8;h++){ int bh=b*8+h; rkv[h]=rk[(size_t)bh*Mm+m]; k1v[h]=k1[(size_t)bh*Mm+m]; k2v[h]=k2[(size_t)bh*Mm+m]; }
    const unsigned* bb=bits+(size_t)b*sb+blockIdx.x*4;
    for(int n0=nbase;n0<nbase+256;n0+=32){
        wb[t>>2][t&3]=bb[(size_t)(n0+(t>>2))*bld+(t&3)];
        for(int i=t;i<768;i+=128){
            int which=i>>8, r=i&255, h=r>>5, nn=r&31;
            const float* src=which==0?rq:(which==1?q1:q2);
            qt[which][h][nn]=src[(size_t)(b*8+h)*Nn+n0+nn];
        }
        __syncthreads();
        int mw=t>>5, msh=t&31;
        for(int nn=0;nn<32;nn++){
            if((wb[nn][mw]>>msh)&1u){
                #pragma unroll
                for(int h=0;h<8;h++){
                    bool c=qt[0][h][nn]+rkv[h]>0.f;
                    acc[h]+= c? qt[1][h][nn]*k1v[h] : qt[2][h][nn]*k2v[h];
                }
            }
        }
        __syncthreads();
    }
    #pragma unroll
    for(int h=0;h<8;h++) ps[((size_t)(b*8+h)*Mm+m)*nch+blockIdx.y]=acc[h];
}
__global__ void csmerge_k(const float* __restrict__ ps, float* __restrict__ cs, int Mm, int nch){
    int idx=blockIdx.x*256+threadIdx.x; if(idx>=NB*HH*Mm) return;
    float s=0.f;
    for(int c=0;c<nch;c++) s+=ps[(size_t)idx*nch+c];
    cs[idx]=(s>0.f)?(1.f/s):0.f;
}

// ============ bf16-split mma.sync GEMM, all-pre-split operands, 1 sync/iter ============
struct GP {
    int M,N,K1,K2,Hdiv;
    const bf *A1H,*A1L,*A2H,*A2L;
    const float *B1; int ldb1, ldc;
    const bf *BH[2],*BL[2];
    float* C; bf *CH,*CL;
    const float *E1,*E2,*scv;
    const float *qr,*qe1,*qe2,*kr,*ke1,*ke2;
    long long sB_b,sB_h,sC_b,sC_h,sSc;
    const unsigned* bits; int bld; long long sBits_b;
};
__device__ __forceinline__ void mma16816(float* c, const unsigned* a, const unsigned* b){
    asm volatile("mma.sync.aligned.m16n8k16.row.col.f32.bf16.bf16.f32 "
        "{%0,%1,%2,%3},{%4,%5,%6,%7},{%8,%9},{%0,%1,%2,%3};"
        : "+f"(c[0]),"+f"(c[1]),"+f"(c[2]),"+f"(c[3])
        : "r"(a[0]),"r"(a[1]),"r"(a[2]),"r"(a[3]),"r"(b[0]),"r"(b[1]));
}
#define LDSM4(d,a) asm volatile("ldmatrix.sync.aligned.m8n8.x4.shared.b16 {%0,%1,%2,%3},[%4];":"=r"((d)[0]),"=r"((d)[1]),"=r"((d)[2]),"=r"((d)[3]):"r"(a))
#define LDSM4T(d,a) asm volatile("ldmatrix.sync.aligned.m8n8.x4.trans.shared.b16 {%0,%1,%2,%3},[%4];":"=r"((d)[0]),"=r"((d)[1]),"=r"((d)[2]),"=r"((d)[3]):"r"(a))
#define SWZA(r,c) (((r)<<5)+((((c)>>3)^(((r)>>1)&3))<<3)+((c)&7))
#define SWZB(r,c) (((r)<<6)+((((c)>>3)^((r)&7))<<3)+((c)&7))
constexpr int A_H=128*32, B_H=32*64;
constexpr int OFF_AL=A_H, OFF_BH=2*A_H, OFF_BL=2*A_H+B_H;
constexpr int SSTR=2*A_H+2*B_H;
constexpr int SMB=2*SSTR*2+3*1024*4;

template<int ASRC,int EPI,int BPRE>
__global__ void __launch_bounds__(256) gemm_k(GP p){
    extern __shared__ bf sm[];
    const int t=threadIdx.x, lane=t&31, wid=t>>5;
    const int wm=wid&3, wn=wid>>2, g=lane>>2, tc=lane&3;
    const int m0=blockIdx.x*128, n0=blockIdx.y*64, z=blockIdx.z;
    const int zb=z/p.Hdiv, zh=z-zb*p.Hdiv;
    const float* B1=p.B1?(p.B1+zb*p.sB_b+zh*p.sB_h):nullptr;
    float* C=p.C+zb*p.sC_b+zh*p.sC_h;
    bf* CHp=p.CH?(p.CH+zb*p.sC_b+zh*p.sC_h):nullptr;
    bf* CLp=p.CL?(p.CL+zb*p.sC_b+zh*p.sC_h):nullptr;
    const unsigned* bitsp=nullptr;
    if(ASRC!=0) bitsp=p.bits+zb*p.sBits_b;
    const bf *bhB[2]={nullptr,nullptr},*blB[2]={nullptr,nullptr};
    if(BPRE){
        bhB[0]=p.BH[0]+zb*p.sB_b; blB[0]=p.BL[0]+zb*p.sB_b;
        if(p.BH[1]){ bhB[1]=p.BH[1]+zb*p.sB_b; blB[1]=p.BL[1]+zb*p.sB_b; }
    }
    const float* scv=(ASRC==2)?(p.scv+(long long)z*p.sSc):nullptr;
    const int Ktot=p.K1+p.K2, niter=Ktot>>5;
    float acc[2][4][4]={};
    uint4 rAH[2],rAL[2],rBH,rBL; float rB[8]; unsigned rW=0;
    const int ar=t>>1, akq=(t&1)*16;
    const int br=t>>3, bnq=(t&7)*8;
    const int wk=t&31, wsel=t>>5;
    float rqv=0.f,q1v=0.f,q2v=0.f;
    float* kt=(float*)(sm+2*SSTR);
    unsigned smb=(unsigned)__cvta_generic_to_shared(sm);
    unsigned aAddr[2][2], bAddr[2][2];
    {
        int rA_=wm*32+(lane&15), cgA=(lane>>4)*8;
        #pragma unroll
        for(int mt=0;mt<2;mt++)
            #pragma unroll
            for(int k2=0;k2<2;k2++) aAddr[mt][k2]=smb+2u*SWZA(rA_+mt*16, cgA+k2*16);
        int rB_=(lane&7)+((lane>>3)&1)*8, cB=wn*32+(lane>>4)*8;
        #pragma unroll
        for(int pp=0;pp<2;pp++)
            #pragma unroll
            for(int k2=0;k2<2;k2++) bAddr[pp][k2]=smb+2u*(OFF_BH+SWZB(rB_+k2*16, cB+pp*16));
    }
    if(ASRC==2){
        long long qo=(long long)z*p.M; int n=m0+ar;
        rqv=p.qr[qo+n]; q1v=p.qe1[qo+n]; q2v=p.qe2[qo+n];
        long long ko=(long long)z*p.K1;
        for(int i=t;i<p.K1;i+=256){
            kt[i]=p.kr[ko+i]; kt[p.K1+i]=p.ke1[ko+i]; kt[2*p.K1+i]=p.ke2[ko+i];
        }
        __syncthreads();
    }

    auto loadregs=[&](int it){
        int kk=it<<5;
        if(ASRC==0){
            const bf *ah,*al; int ko;
            if(kk<p.K1){ah=p.A1H; al=p.A1L; ko=kk;} else {ah=p.A2H; al=p.A2L; ko=kk-p.K1;}
            long long off=(long long)(m0+ar)*512+ko+akq;
            rAH[0]=*(const uint4*)(ah+off); rAH[1]=*(const uint4*)(ah+off+8);
            rAL[0]=*(const uint4*)(al+off); rAL[1]=*(const uint4*)(al+off+8);
        } else if(ASRC==1){
            rW=bitsp[(long long)(kk+wk)*p.bld+((unsigned)m0>>5)+(wsel>>1)];
        } else {
            rW=bitsp[(size_t)(m0+ar)*p.bld+(kk>>5)];
        }
        if(BPRE){
            int sec=(kk>=p.K1)?1:0, ko=sec?kk-p.K1:kk;
            long long off=(long long)(ko+br)*512+n0+bnq;
            rBH=*(const uint4*)(bhB[sec]+off);
            rBL=*(const uint4*)(blB[sec]+off);
        } else {
            const float* s=B1+(long long)(kk+br)*p.ldb1+n0+bnq;
            *(float4*)(rB)=*(const float4*)(s);
            *(float4*)(rB+4)=*(const float4*)(s+4);
            if(ASRC==2){
                float scl=scv[kk+br];
                #pragma unroll
                for(int i=0;i<8;i++) rB[i]*=scl;
            }
        }
    };
    auto storesm=[&](int buf,int kk){
        bf* base=sm+buf*SSTR;
        if(ASRC==0){
            int o0=SWZA(ar,akq), o1=SWZA(ar,akq+8);
            *(uint4*)(base+o0)=rAH[0]; *(uint4*)(base+o1)=rAH[1];
            *(uint4*)(base+OFF_AL+o0)=rAL[0]; *(uint4*)(base+OFF_AL+o1)=rAL[1];
        } else if(ASRC==1){
            int mb=wsel*16, sh=(wsel&1)*16;
            #pragma unroll
            for(int i=0;i<16;i++)
                base[SWZA(mb+i,wk)]=__float2bfloat16_rn((float)((rW>>(sh+i))&1u));
        } else {
            #pragma unroll
            for(int i=0;i<16;i++){
                float v=0.f;
                if((rW>>(akq+i))&1u){
                    int mI=kk+akq+i;
                    v=(rqv+kt[mI]>0.f)?(q1v*kt[p.K1+mI]):(q2v*kt[2*p.K1+mI]);
                }
                bf h=__float2bfloat16_rn(v);
                int o=SWZA(ar,akq+i);
                base[o]=h; base[OFF_AL+o]=__float2bfloat16_rn(v-__bfloat162float(h));
            }
        }
        int o=SWZB(br,bnq);
        if(BPRE){
            *(uint4*)(base+OFF_BH+o)=rBH;
            *(uint4*)(base+OFF_BL+o)=rBL;
        } else {
            __nv_bfloat162 hp[4], lp[4];
            #pragma unroll
            for(int j=0;j<4;j++){
                float x0=rB[2*j], x1=rB[2*j+1];
                bf h0=__float2bfloat16_rn(x0), h1=__float2bfloat16_rn(x1);
                hp[j]=__nv_bfloat162(h0,h1);
                lp[j]=__nv_bfloat162(__float2bfloat16_rn(x0-__bfloat162float(h0)),
                                     __float2bfloat16_rn(x1-__bfloat162float(h1)));
            }
            *(uint4*)(base+OFF_BH+o)=*(uint4*)hp;
            *(uint4*)(base+OFF_BL+o)=*(uint4*)lp;
        }
    };

    loadregs(0);
    for(int it=0;it<niter;it++){
        int buf=it&1;
        storesm(buf,it<<5);
        __syncthreads();
        if(it+1<niter) loadregs(it+1);
        unsigned bo=(unsigned)buf*SSTR*2u;
        #pragma unroll
        for(int k2=0;k2<2;k2++){
            unsigned aH[2][4], aL[2][4], bH[2][4], bL[2][4];
            #pragma unroll
            for(int mt=0;mt<2;mt++){
                LDSM4(aH[mt], aAddr[mt][k2]+bo);
                if(ASRC!=1) LDSM4(aL[mt], aAddr[mt][k2]+bo+2u*OFF_AL);
            }
            #pragma unroll
            for(int pp=0;pp<2;pp++){
                LDSM4T(bH[pp], bAddr[pp][k2]+bo);
                LDSM4T(bL[pp], bAddr[pp][k2]+bo+2u*(OFF_BL-OFF_BH));
            }
            #pragma unroll
            for(int mt=0;mt<2;mt++)
                #pragma unroll
                for(int nt=0;nt<4;nt++){
                    const unsigned* bh=&bH[nt>>1][(nt&1)*2];
                    const unsigned* bl=&bL[nt>>1][(nt&1)*2];
                    mma16816(acc[mt][nt],aH[mt],bh);
                    mma16816(acc[mt][nt],aH[mt],bl);
                    if(ASRC!=1) mma16816(acc[mt][nt],aL[mt],bh);
                }
        }
        // NOTE: no second __syncthreads() — with 2 buffers, the write to buf in
        // iter it+2 is ordered after the it+1 barrier, and every warp finished
        // computing from buf (iter it) before arriving at that barrier.
    }
    #pragma unroll
    for(int mt=0;mt<2;mt++)
        #pragma unroll
        for(int nt=0;nt<4;nt++)
            #pragma unroll
            for(int hrow=0;hrow<2;hrow++){
                long long r=m0+wm*32+mt*16+g+hrow*8;
                int col=n0+wn*32+nt*8+tc*2;
                float x0=acc[mt][nt][hrow*2], x1=acc[mt][nt][hrow*2+1];
                float2 o;
                if(EPI==1){
                    float2 v1=*(const float2*)(p.E1+r*p.ldc+col);
                    float2 v2=*(const float2*)(p.E2+r*p.ldc+col);
                    float f0=1.f/(1.f+__expf(-x0)), f1=1.f/(1.f+__expf(-x1));
                    o.x=v2.x+f0*(v1.x-v2.x); o.y=v2.y+f1*(v1.y-v2.y);
                } else if(EPI==2){
                    o.x=x0>0.f?x0:__expf(x0)-1.f; o.y=x1>0.f?x1:__expf(x1)-1.f;
                } else { o.x=x0; o.y=x1; }
                *(float2*)(C+r*p.ldc+col)=o;
                if(CHp){
                    bf h0=__float2bfloat16_rn(o.x), h1=__float2bfloat16_rn(o.y);
                    *(__nv_bfloat162*)(CHp+r*p.ldc+col)=__nv_bfloat162(h0,h1);
                    *(__nv_bfloat162*)(CLp+r*p.ldc+col)=__nv_bfloat162(
                        __float2bfloat16_rn(o.x-__bfloat162float(h0)),
                        __float2bfloat16_rn(o.y-__bfloat162float(h1)));
                }
            }
}

static void proj_go(Tens X,int rows,const bf* WH,const bf* WL,float* out){
    GP p{}; p.M=rows; p.N=512; p.K1=512; p.Hdiv=1;
    p.A1H=X.h; p.A1L=X.l; p.BH[0]=WH; p.BL[0]=WL; p.C=out; p.ldc=512;
    gemm_k<0,0,1><<<dim3(rows/128,8,1),256,SMB>>>(p);
}
static void fusion_go(Tens a,Tens bm,int rows,
                      const bf* FWH,const bf* FWL,size_t woff,
                      float* P1,float* out,bf* outH,bf* outL){
    GP p{}; p.M=rows; p.N=512; p.K1=512; p.K2=512; p.Hdiv=1;
    p.A1H=a.h; p.A1L=a.l; p.A2H=bm.h; p.A2L=bm.l;
    p.BH[0]=FWH+0*2097152+woff; p.BH[1]=FWH+1*2097152+woff;
    p.BL[0]=FWL+0*2097152+woff; p.BL[1]=FWL+1*2097152+woff;
    p.C=P1; p.ldc=512;
    gemm_k<0,0,1><<<dim3(rows/128,8,1),256,SMB>>>(p);
    p.BH[0]=FWH+2*2097152+woff; p.BH[1]=FWH+3*2097152+woff;
    p.BL[0]=FWL+2*2097152+woff; p.BL[1]=FWL+3*2097152+woff;
    p.C=out; p.CH=outH; p.CL=outL; p.E1=P1; p.E2=a.f;
    gemm_k<0,1,1><<<dim3(rows/128,8,1),256,SMB>>>(p);
}
static void attn_go(float* S,Tens q,int Nqq,Tens kv,int Nkv,
                    const bf* WH,const bf* WL,const float* a1,const float* a2,
                    const unsigned* bits,int bld,long long sb,
                    float* agg,bf* aggH,bf* aggL){
    float *projQ=S+O_PJQ,*projK=S+O_PJK;
    float *rq=S+O_EQ,*rk=S+O_EK,*q1=S+O_Q1,*k1=S+O_K1,*q2=S+O_Q2,*k2=S+O_K2;
    float *cs=S+O_CSC,*ps=S+O_PS;
    proj_go(q,NB*Nqq,WH,WL,projQ);
    proj_go(kv,NB*Nkv,WH,WL,projK);
    dot_a_k<<<(NB*HH*Nqq+255)/256,256>>>(projQ,a1,rq,q1,q2,Nqq);
    dot_a_k<<<(NB*HH*Nkv+255)/256,256>>>(projK,a2,rk,k1,k2,Nkv);
    int nch=Nqq/256;
    bitsum_k<<<dim3(Nkv/128,nch,NB),128>>>(bits,rq,q1,q2,rk,k1,k2,ps,Nqq,Nkv,bld,nch,sb);
    csmerge_k<<<(NB*HH*Nkv+255)/256,256>>>(ps,cs,Nkv,nch);
    GP p{}; p.M=Nqq; p.N=64; p.K1=Nkv; p.Hdiv=HH;
    p.B1=projK; p.ldb1=512; p.sB_b=(long long)Nkv*512; p.sB_h=64;
    p.C=agg; p.ldc=512; p.sC_b=(long long)Nqq*512; p.sC_h=64;
    p.CH=aggH; p.CL=aggL;
    p.scv=cs; p.sSc=Nkv;
    p.qr=rq; p.qe1=q1; p.qe2=q2; p.kr=rk; p.ke1=k1; p.ke2=k2;
    p.bits=bits; p.bld=bld; p.sBits_b=sb;
    gemm_k<2,2,0><<<dim3(Nqq/128,1,NB*HH),256,SMB>>>(p);
}

extern "C" void kernel_launch(void* const* d_in, const int* in_sizes, int n_in,
                              void* d_out, int out_size){
    cudaFuncSetAttribute(gemm_k<0,0,1>,cudaFuncAttributeMaxDynamicSharedMemorySize,SMB);
    cudaFuncSetAttribute(gemm_k<0,1,1>,cudaFuncAttributeMaxDynamicSharedMemorySize,SMB);
    cudaFuncSetAttribute(gemm_k<1,0,1>,cudaFuncAttributeMaxDynamicSharedMemorySize,SMB);
    cudaFuncSetAttribute(gemm_k<2,2,0>,cudaFuncAttributeMaxDynamicSharedMemorySize,SMB);
    float* S; cudaGetSymbolAddress((void**)&S, d_scratch);
    const float* in_g=(const float*)d_in[0];
    const float* in_c=(const float*)d_in[1];
    const float* in_q=(const float*)d_in[2];
    const int* adj_gc=(const int*)d_in[3];
    const int* adj_gq=(const int*)d_in[4];
    const float* aW[3]={(const float*)d_in[5],(const float*)d_in[8],(const float*)d_in[11]};
    const float* aa1[3]={(const float*)d_in[6],(const float*)d_in[9],(const float*)d_in[12]};
    const float* aa2[3]={(const float*)d_in[7],(const float*)d_in[10],(const float*)d_in[13]};
    const float* fus[4]={(const float*)d_in[14],(const float*)d_in[15],(const float*)d_in[16],(const float*)d_in[17]};
    float* out=(float*)d_out;

    unsigned* bgc=(unsigned*)(S+O_BGC);
    unsigned* bgq=(unsigned*)(S+O_BGQ);
    unsigned* bgqT=(unsigned*)(S+O_BGQT);
    bf* WTH=(bf*)(S+O_WTH); bf* WTL=(bf*)(S+O_WTL);
    bf* FWH=(bf*)(S+O_FWH); bf* FWL=(bf*)(S+O_FWL);
    #define BFP(o) ((bf*)(S+(o)))
    float *gsame=S+O_GS, *agg=S+O_AGG, *P1=S+O_P1, *G1f=S+O_G1;

    bitpack_k<<<512,256>>>(adj_gc,bgc,131072);
    bitpack_k<<<128,256>>>(adj_gq,bgq,32768);
    bitpackT_k<<<128,256>>>(adj_gq,bgqT);
    repack3_k<<<(3*2*HH*FF*DD+255)/256,256>>>(aW[0],aW[1],aW[2],WTH,WTL);
    {
        WS w{};
        for(int i=0;i<4;i++){ w.src[i]=fus[i]; w.h[i]=FWH+(size_t)i*2097152; w.l[i]=FWL+(size_t)i*2097152; w.n[i]=2097152; }
        w.src[4]=in_g; w.h[4]=BFP(O_IGH); w.l[4]=BFP(O_IGL); w.n[4]=2097152;
        w.src[5]=in_c; w.h[5]=BFP(O_ICH); w.l[5]=BFP(O_ICL); w.n[5]=2097152;
        w.src[6]=in_q; w.h[6]=BFP(O_IQH); w.l[6]=BFP(O_IQL); w.n[6]=524288;
        wsplit_all<<<dim3(8192,7),256>>>(w);
    }

    Tens GS={gsame,BFP(O_GSH),BFP(O_GSL)};
    Tens AG={agg,BFP(O_AGH),BFP(O_AGL)};
    Tens G1={G1f,BFP(O_G1H),BFP(O_G1L)};

    for(int l=0;l<2;l++){
        Tens G,C,Q; float *Gout,*Cout,*Qout; bf *GoH,*GoL,*CoH,*CoL,*QoH,*QoL;
        if(l==0){
            G={in_g,BFP(O_IGH),BFP(O_IGL)}; C={in_c,BFP(O_ICH),BFP(O_ICL)}; Q={in_q,BFP(O_IQH),BFP(O_IQL)};
            Gout=S+O_G0; Cout=S+O_C0; Qout=S+O_Q0;
            GoH=BFP(O_G0H); GoL=BFP(O_G0L); CoH=BFP(O_C0H); CoL=BFP(O_C0L); QoH=BFP(O_Q0H); QoL=BFP(O_Q0L);
        } else {
            G={S+O_G0,BFP(O_G0H),BFP(O_G0L)}; C={S+O_C0,BFP(O_C0H),BFP(O_C0L)}; Q={S+O_Q0,BFP(O_Q0H),BFP(O_Q0L)};
            Gout=out; Cout=out+SZ_GF; Qout=out+2*SZ_GF;
            GoH=GoL=CoH=CoL=QoH=QoL=nullptr;
        }
        {
            GP p{}; p.M=NC; p.N=512; p.K1=NG; p.Hdiv=1;
            p.bits=bgc; p.bld=NC/32; p.sBits_b=(long long)NG*(NC/32);
            p.BH[0]=G.h; p.BL[0]=G.l; p.sB_b=(long long)NG*512;
            p.C=gsame; p.ldc=512; p.sC_b=(long long)NC*512;
            p.CH=(bf*)GS.h; p.CL=(bf*)GS.l;
            gemm_k<1,0,1><<<dim3(NC/128,8,NB),256,SMB>>>(p);
        }
        fusion_go(C,GS,NB*NC, FWH,FWL,(size_t)(l*4+0)*262144, P1,Cout,CoH,CoL);
        attn_go(S,G,NG,C,NC, WTH+(size_t)(0*2+l)*262144, WTL+(size_t)(0*2+l)*262144,
                aa1[0]+l*HH*DD, aa2[0]+l*HH*DD, bgc,NC/32,(long long)NG*(NC/32),
                agg,(bf*)AG.h,(bf*)AG.l);
        fusion_go(G,AG,NB*NG, FWH,FWL,(size_t)(l*4+1)*262144, P1,G1f,(bf*)G1.h,(bf*)G1.l);
        attn_go(S,Q,NQ,G,NG, WTH+(size_t)(1*2+l)*262144, WTL+(size_t)(1*2+l)*262144,
                aa1[1]+l*HH*DD, aa2[1]+l*HH*DD, bgqT,NG/32,(long long)NQ*(NG/32),
                agg,(bf*)AG.h,(bf*)AG.l);
        fusion_go(Q,AG,NB*NQ, FWH,FWL,(size_t)(l*4+2)*262144, P1,Qout,QoH,QoL);
        attn_go(S,G,NG,Q,NQ, WTH+(size_t)(2*2+l)*262144, WTL+(size_t)(2*2+l)*262144,
                aa1[2]+l*HH*DD, aa2[2]+l*HH*DD, bgq,NQ/32,(long long)NG*(NQ/32),
                agg,(bf*)AG.h,(bf*)AG.l);
        fusion_go(G1,AG,NB*NG, FWH,FWL,(size_t)(l*4+3)*262144, P1,Gout,GoH,GoL);
    }
}

// round 15
// speedup vs baseline: 1.5786x; 1.0419x over previous
#include <cuda_runtime.h>
#include <cuda_bf16.h>
#include <cstdint>

constexpr int NB=4, NG=1024, NC=1024, NQ=256, FF=512, HH=8, DD=64;
constexpr size_t SZ_GF=(size_t)NB*NG*FF, SZ_QF=(size_t)NB*NQ*FF;
constexpr size_t MW=1048576, QW=262144;
constexpr size_t O_G0=0,O_C0=O_G0+SZ_GF,O_Q0=O_C0+SZ_GF,O_G1=O_Q0+SZ_QF,O_GS=O_G1+SZ_GF;
constexpr size_t O_PJQ=O_GS+SZ_GF,O_PJK=O_PJQ+SZ_GF,O_AGG=O_PJK+SZ_GF,O_P1=O_AGG+SZ_GF;
constexpr size_t O_EQ=O_P1+SZ_GF,O_EK=O_EQ+32768,O_Q1=O_EK+32768,O_K1=O_Q1+32768;
constexpr size_t O_Q2=O_K1+32768,O_K2=O_Q2+32768,O_CSC=O_K2+32768,O_PS=O_CSC+32768;
constexpr size_t O_BGC=O_PS+262144,O_BGQ=O_BGC+131072,O_BGQT=O_BGQ+32768;
constexpr size_t O_WTH=O_BGQT+32768,O_WTL=O_WTH+786432;
constexpr size_t O_FWH=O_WTL+786432,O_FWL=O_FWH+4194304;
constexpr size_t B0=O_FWL+4194304;
constexpr size_t O_IGH=B0,O_IGL=O_IGH+MW,O_ICH=O_IGL+MW,O_ICL=O_ICH+MW;
constexpr size_t O_IQH=O_ICL+MW,O_IQL=O_IQH+QW;
constexpr size_t O_G0H=O_IQL+QW,O_G0L=O_G0H+MW,O_C0H=O_G0L+MW,O_C0L=O_C0H+MW;
constexpr size_t O_Q0H=O_C0L+MW,O_Q0L=O_Q0H+QW,O_G1H=O_Q0L+QW,O_G1L=O_G1H+MW;
constexpr size_t O_GSH=O_G1L+MW,O_GSL=O_GSH+MW,O_AGH=O_GSL+MW,O_AGL=O_AGH+MW;
constexpr size_t S_TOT=O_AGL+MW;
__device__ float d_scratch[S_TOT];

typedef __nv_bfloat16 bf;
struct Tens{ const float* f; const bf *h,*l; };

__global__ void bitpack_k(const int* __restrict__ adj, unsigned* __restrict__ bits, int nwords){
    int w=blockIdx.x*256+threadIdx.x; if(w>=nwords) return;
    const int* p=adj+(size_t)w*32; unsigned v=0;
    #pragma unroll
    for(int i=0;i<32;i++) v|=(p[i]>0?1u:0u)<<i;
    bits[w]=v;
}
__global__ void bitpackT_k(const int* __restrict__ adj, unsigned* __restrict__ bits){
    int idx=blockIdx.x*256+threadIdx.x; if(idx>=NB*NQ*(NG/32)) return;
    int gw=idx&31, q=(idx>>5)&255, b=idx>>13;
    unsigned v=0;
    for(int i=0;i<32;i++) v|=(adj[((size_t)b*NG+gw*32+i)*NQ+q]>0?1u:0u)<<i;
    bits[(size_t)b*NQ*32+(size_t)q*32+gw]=v;
}
__global__ void repack3_k(const float* __restrict__ W0,const float* __restrict__ W1,
                          const float* __restrict__ W2, bf* __restrict__ hi, bf* __restrict__ lo){
    int i=blockIdx.x*256+threadIdx.x; if(i>=3*2*HH*FF*DD) return;
    int tp=i>>19, j=i&524287;
    int d=j&63, f=(j>>6)&511, h=(j>>15)&7, l=j>>18;
    const float* W=tp==0?W0:(tp==1?W1:W2);
    float v=W[j];
    size_t o=(size_t)tp*2*FF*512+((size_t)(l*FF+f))*512+h*64+d;
    bf hh=__float2bfloat16_rn(v);
    hi[o]=hh; lo[o]=__float2bfloat16_rn(v-__bfloat162float(hh));
}
struct WS{ const float* src[7]; bf *h[7],*l[7]; int n[7]; };
__global__ void wsplit_all(WS w){
    int s=blockIdx.y;
    int i=blockIdx.x*256+threadIdx.x; if(i>=w.n[s]) return;
    float v=w.src[s][i];
    bf h=__float2bfloat16_rn(v);
    w.h[s][i]=h; w.l[s][i]=__float2bfloat16_rn(v-__bfloat162float(h));
}
__global__ void dot_a_k(const float* __restrict__ X, const float* __restrict__ a,
                        float* __restrict__ raw, float* __restrict__ e1, float* __restrict__ e2, int N){
    int idx=blockIdx.x*256+threadIdx.x; if(idx>=NB*HH*N) return;
    int n=idx%N, h=(idx/N)%HH, b=idx/(N*HH);
    const float* xp=X+((size_t)(b*N+n))*FF+h*DD; const float* ap=a+h*DD;
    float s=0.f;
    #pragma unroll
    for(int i=0;i<DD;i+=4){
        float4 xv=*(const float4*)(xp+i); float4 av=*(const float4*)(ap+i);
        s+=xv.x*av.x+xv.y*av.y+xv.z*av.z+xv.w*av.w;
    }
    raw[idx]=s; e1[idx]=__expf(s); e2[idx]=__expf(0.2f*s);
}
__global__ void bitsum_k(const unsigned* __restrict__ bits,
    const float* __restrict__ rq,const float* __restrict__ q1,const float* __restrict__ q2,
    const float* __restrict__ rk,const float* __restrict__ k1,const float* __restrict__ k2,
    float* __restrict__ ps, int Nn,int Mm,int bld,int nch,long long sb){
    __shared__ unsigned wb[32][4];
    __shared__ float qt[3][8][32];
    int t=threadIdx.x, m=blockIdx.x*128+t, b=blockIdx.z;
    int nbase=blockIdx.y*256;
    float acc[8]={}; float rkv[8],k1v[8],k2v[8];
    #pragma unroll
    for(int h=0;h<8;h++){ int bh=b*8+h; rkv[h]=rk[(size_t)bh*Mm+m]; k1v[h]=k1[(size_t)bh*Mm+m]; k2v[h]=k2[(size_t)bh*Mm+m]; }
    const unsigned* bb=bits+(size_t)b*sb+blockIdx.x*4;
    for(int n0=nbase;n0<nbase+256;n0+=32){
        wb[t>>2][t&3]=bb[(size_t)(n0+(t>>2))*bld+(t&3)];
        for(int i=t;i<768;i+=128){
            int which=i>>8, r=i&255, h=r>>5, nn=r&31;
            const float* src=which==0?rq:(which==1?q1:q2);
            qt[which][h][nn]=src[(size_t)(b*8+h)*Nn+n0+nn];
        }
        __syncthreads();
        int mw=t>>5, msh=t&31;
        for(int nn=0;nn<32;nn++){
            if((wb[nn][mw]>>msh)&1u){
                #pragma unroll
                for(int h=0;h<8;h++){
                    bool c=qt[0][h][nn]+rkv[h]>0.f;
                    acc[h]+= c? qt[1][h][nn]*k1v[h] : qt[2][h][nn]*k2v[h];
                }
            }
        }
        __syncthreads();
    }
    #pragma unroll
    for(int h=0;h<8;h++) ps[((size_t)(b*8+h)*Mm+m)*nch+blockIdx.y]=acc[h];
}
__global__ void csmerge_k(const float* __restrict__ ps, float* __restrict__ cs, int Mm, int nch){
    int idx=blockIdx.x*256+threadIdx.x; if(idx>=NB*HH*Mm) return;
    float s=0.f;
    for(int c=0;c<nch;c++) s+=ps[(size_t)idx*nch+c];
    cs[idx]=(s>0.f)?(1.f/s):0.f;
}

struct GP {
    int M,N,K1,K2,Hdiv;
    const bf *A1H,*A1L,*A2H,*A2L;
    const float *B1; int ldb1, ldc;
    const bf *BH[2],*BL[2];
    float* C; bf *CH,*CL;
    const float *E1,*E2,*scv;
    const float *qr,*qe1,*qe2,*kr,*ke1,*ke2;
    long long sB_b,sB_h,sC_b,sC_h,sSc;
    const unsigned* bits; int bld; long long sBits_b;
};
__device__ __forceinline__ void mma16816(float* c, const unsigned* a, const unsigned* b){
    asm volatile("mma.sync.aligned.m16n8k16.row.col.f32.bf16.bf16.f32 "
        "{%0,%1,%2,%3},{%4,%5,%6,%7},{%8,%9},{%0,%1,%2,%3};"
        : "+f"(c[0]),"+f"(c[1]),"+f"(c[2]),"+f"(c[3])
        : "r"(a[0]),"r"(a[1]),"r"(a[2]),"r"(a[3]),"r"(b[0]),"r"(b[1]));
}
#define LDSM4(d,a) asm volatile("ldmatrix.sync.aligned.m8n8.x4.shared.b16 {%0,%1,%2,%3},[%4];":"=r"((d)[0]),"=r"((d)[1]),"=r"((d)[2]),"=r"((d)[3]):"r"(a))
#define LDSM4T(d,a) asm volatile("ldmatrix.sync.aligned.m8n8.x4.trans.shared.b16 {%0,%1,%2,%3},[%4];":"=r"((d)[0]),"=r"((d)[1]),"=r"((d)[2]),"=r"((d)[3]):"r"(a))
#define CPA16(d,s) asm volatile("cp.async.cg.shared.global [%0],[%1],16;"::"r"(d),"l"(s))
#define CPCOMMIT() asm volatile("cp.async.commit_group;":::"memory")
#define CPWAIT1()  asm volatile("cp.async.wait_group 1;":::"memory")
#define SWZA(r,c) (((r)<<5)+((((c)>>3)^(((r)>>1)&3))<<3)+((c)&7))
#define SWZB(r,c) (((r)<<6)+((((c)>>3)^((r)&7))<<3)+((c)&7))
constexpr int A_H=128*32, B_H=32*64;
constexpr int OFF_AL=A_H, OFF_BH=2*A_H, OFF_BL=2*A_H+B_H;
constexpr int SSTR=2*A_H+2*B_H;
constexpr unsigned SSTRB=SSTR*2;
constexpr int SMB=3*SSTR*2;

template<int ASRC,int EPI,int BPRE>
__global__ void __launch_bounds__(256) gemm_k(GP p){
    extern __shared__ bf sm[];
    const int t=threadIdx.x, lane=t&31, wid=t>>5;
    const int wm=wid&3, wn=wid>>2, g=lane>>2, tc=lane&3;
    const int m0=blockIdx.x*128, n0=blockIdx.y*64, z=blockIdx.z;
    const int zb=z/p.Hdiv, zh=z-zb*p.Hdiv;
    const float* B1=p.B1?(p.B1+zb*p.sB_b+zh*p.sB_h):nullptr;
    float* C=p.C+zb*p.sC_b+zh*p.sC_h;
    bf* CHp=p.CH?(p.CH+zb*p.sC_b+zh*p.sC_h):nullptr;
    bf* CLp=p.CL?(p.CL+zb*p.sC_b+zh*p.sC_h):nullptr;
    const unsigned* bitsp=nullptr;
    if(ASRC!=0) bitsp=p.bits+zb*p.sBits_b;
    const bf *bhB[2]={nullptr,nullptr},*blB[2]={nullptr,nullptr};
    if(BPRE){
        bhB[0]=p.BH[0]+zb*p.sB_b; blB[0]=p.BL[0]+zb*p.sB_b;
        if(p.BH[1]){ bhB[1]=p.BH[1]+zb*p.sB_b; blB[1]=p.BL[1]+zb*p.sB_b; }
    }
    const float* scv=(ASRC==2)?(p.scv+(long long)z*p.sSc):nullptr;
    const int Ktot=p.K1+p.K2, niter=Ktot>>5;
    float acc[2][4][4]={};
    const int ar=t>>1, akq=(t&1)*16;
    const int br=t>>3, bnq=(t&7)*8;
    const int wk=t&31, wsel=t>>5;
    float rqv=0.f,q1v=0.f,q2v=0.f;
    float* kt=(float*)(sm+2*SSTR);
    unsigned smb=(unsigned)__cvta_generic_to_shared(sm);
    unsigned aAddr[2][2], bAddr[2][2];
    {
        int rA_=wm*32+(lane&15), cgA=(lane>>4)*8;
        #pragma unroll
        for(int mt=0;mt<2;mt++)
            #pragma unroll
            for(int k2=0;k2<2;k2++) aAddr[mt][k2]=smb+2u*SWZA(rA_+mt*16, cgA+k2*16);
        int rB_=(lane&7)+((lane>>3)&1)*8, cB=wn*32+(lane>>4)*8;
        #pragma unroll
        for(int pp=0;pp<2;pp++)
            #pragma unroll
            for(int k2=0;k2<2;k2++) bAddr[pp][k2]=smb+2u*(OFF_BH+SWZB(rB_+k2*16, cB+pp*16));
    }
    const unsigned cpA0=2u*SWZA(ar,akq), cpA1=2u*SWZA(ar,akq+8);
    const unsigned cpAL0=2u*(OFF_AL+SWZA(ar,akq)), cpAL1=2u*(OFF_AL+SWZA(ar,akq+8));
    const unsigned cpB0=2u*(OFF_BH+SWZB(br,bnq)), cpB1=2u*(OFF_BL+SWZB(br,bnq));
    if(ASRC==2){
        long long qo=(long long)z*p.M; int n=m0+ar;
        rqv=p.qr[qo+n]; q1v=p.qe1[qo+n]; q2v=p.qe2[qo+n];
        long long ko=(long long)z*p.K1;
        for(int i=t;i<p.K1;i+=256){
            kt[i]=p.kr[ko+i]; kt[p.K1+i]=p.ke1[ko+i]; kt[2*p.K1+i]=p.ke2[ko+i];
        }
        __syncthreads();
    }

    auto compute_buf=[&](unsigned bo){
        #pragma unroll
        for(int k2=0;k2<2;k2++){
            unsigned aH[2][4], aL[2][4], bH[2][4], bL[2][4];
            #pragma unroll
            for(int mt=0;mt<2;mt++){
                LDSM4(aH[mt], aAddr[mt][k2]+bo);
                if(ASRC!=1) LDSM4(aL[mt], aAddr[mt][k2]+bo+2u*OFF_AL);
            }
            #pragma unroll
            for(int pp=0;pp<2;pp++){
                LDSM4T(bH[pp], bAddr[pp][k2]+bo);
                LDSM4T(bL[pp], bAddr[pp][k2]+bo+2u*(OFF_BL-OFF_BH));
            }
            #pragma unroll
            for(int mt=0;mt<2;mt++)
                #pragma unroll
                for(int nt=0;nt<4;nt++){
                    const unsigned* bh=&bH[nt>>1][(nt&1)*2];
                    const unsigned* bl=&bL[nt>>1][(nt&1)*2];
                    mma16816(acc[mt][nt],aH[mt],bh);
                    mma16816(acc[mt][nt],aH[mt],bl);
                    if(ASRC!=1) mma16816(acc[mt][nt],aL[mt],bh);
                }
        }
    };

    if(ASRC==0){
        auto issue_stage=[&](int st){
            int kk=st<<5;
            const bf *ah,*al;
            int ko;
            if(kk<p.K1){ah=p.A1H; al=p.A1L; ko=kk;} else {ah=p.A2H; al=p.A2L; ko=kk-p.K1;}
            long long off=(long long)(m0+ar)*512+ko+akq;
            unsigned d=smb+((unsigned)(st%3))*SSTRB;
            CPA16(d+cpA0, ah+off);  CPA16(d+cpA1, ah+off+8);
            CPA16(d+cpAL0, al+off); CPA16(d+cpAL1, al+off+8);
            int sec=(kk>=p.K1)?1:0, kb=sec?kk-p.K1:kk;
            long long boff=(long long)(kb+br)*512+n0+bnq;
            CPA16(d+cpB0, bhB[sec]+boff);
            CPA16(d+cpB1, blB[sec]+boff);
            CPCOMMIT();
        };
        issue_stage(0); issue_stage(1);
        for(int it=0;it<niter;it++){
            CPWAIT1();
            __syncthreads();
            if(it+2<niter) issue_stage(it+2);
            compute_buf(((unsigned)(it%3))*SSTRB);
        }
    } else {
        unsigned rW=0; uint4 rBH,rBL; float rB[8];
        auto loadregs=[&](int it){
            int kk=it<<5;
            if(ASRC==1) rW=bitsp[(long long)(kk+wk)*p.bld+((unsigned)m0>>5)+(wsel>>1)];
            else        rW=bitsp[(size_t)(m0+ar)*p.bld+(kk>>5)];
            if(BPRE){
                long long off=(long long)(kk+br)*512+n0+bnq;
                rBH=*(const uint4*)(bhB[0]+off);
                rBL=*(const uint4*)(blB[0]+off);
            } else {
                const float* s=B1+(long long)(kk+br)*p.ldb1+n0+bnq;
                *(float4*)(rB)=*(const float4*)(s);
                *(float4*)(rB+4)=*(const float4*)(s+4);
                if(ASRC==2){
                    float scl=scv[kk+br];
                    #pragma unroll
                    for(int i=0;i<8;i++) rB[i]*=scl;
                }
            }
        };
        auto storesm=[&](int buf,int kk){
            bf* base=sm+buf*SSTR;
            if(ASRC==1){
                int mb=wsel*16, sh=(wsel&1)*16;
                #pragma unroll
                for(int i=0;i<16;i++)
                    base[SWZA(mb+i,wk)]=__float2bfloat16_rn((float)((rW>>(sh+i))&1u));
            } else {
                #pragma unroll
                for(int i=0;i<16;i++){
                    float v=0.f;
                    if((rW>>(akq+i))&1u){
                        int mI=kk+akq+i;
                        v=(rqv+kt[mI]>0.f)?(q1v*kt[p.K1+mI]):(q2v*kt[2*p.K1+mI]);
                    }
                    bf h=__float2bfloat16_rn(v);
                    int o=SWZA(ar,akq+i);
                    base[o]=h; base[OFF_AL+o]=__float2bfloat16_rn(v-__bfloat162float(h));
                }
            }
            int o=SWZB(br,bnq);
            if(BPRE){
                *(uint4*)(base+OFF_BH+o)=rBH;
                *(uint4*)(base+OFF_BL+o)=rBL;
            } else {
                __nv_bfloat162 hp[4], lp[4];
                #pragma unroll
                for(int j=0;j<4;j++){
                    float x0=rB[2*j], x1=rB[2*j+1];
                    bf h0=__float2bfloat16_rn(x0), h1=__float2bfloat16_rn(x1);
                    hp[j]=__nv_bfloat162(h0,h1);
                    lp[j]=__nv_bfloat162(__float2bfloat16_rn(x0-__bfloat162float(h0)),
                                         __float2bfloat16_rn(x1-__bfloat162float(h1)));
                }
                *(uint4*)(base+OFF_BH+o)=*(uint4*)hp;
                *(uint4*)(base+OFF_BL+o)=*(uint4*)lp;
            }
        };
        loadregs(0);
        for(int it=0;it<niter;it++){
            int buf=it&1;
            storesm(buf,it<<5);
            __syncthreads();
            if(it+1<niter) loadregs(it+1);
            compute_buf((unsigned)buf*SSTRB);
        }
    }
    #pragma unroll
    for(int mt=0;mt<2;mt++)
        #pragma unroll
        for(int nt=0;nt<4;nt++)
            #pragma unroll
            for(int hrow=0;hrow<2;hrow++){
                long long r=m0+wm*32+mt*16+g+hrow*8;
                int col=n0+wn*32+nt*8+tc*2;
                float x0=acc[mt][nt][hrow*2], x1=acc[mt][nt][hrow*2+1];
                float2 o;
                if(EPI==1){
                    float2 v1=*(const float2*)(p.E1+r*p.ldc+col);
                    float2 v2=*(const float2*)(p.E2+r*p.ldc+col);
                    float f0=1.f/(1.f+__expf(-x0)), f1=1.f/(1.f+__expf(-x1));
                    o.x=v2.x+f0*(v1.x-v2.x); o.y=v2.y+f1*(v1.y-v2.y);
                } else if(EPI==2){
                    o.x=x0>0.f?x0:__expf(x0)-1.f; o.y=x1>0.f?x1:__expf(x1)-1.f;
                } else { o.x=x0; o.y=x1; }
                *(float2*)(C+r*p.ldc+col)=o;
                if(CHp){
                    bf h0=__float2bfloat16_rn(o.x), h1=__float2bfloat16_rn(o.y);
                    *(__nv_bfloat162*)(CHp+r*p.ldc+col)=__nv_bfloat162(h0,h1);
                    *(__nv_bfloat162*)(CLp+r*p.ldc+col)=__nv_bfloat162(
                        __float2bfloat16_rn(o.x-__bfloat162float(h0)),
                        __float2bfloat16_rn(o.y-__bfloat162float(h1)));
                }
            }
}

static void proj_go(Tens X,int rows,const bf* WH,const bf* WL,float* out){
    GP p{}; p.M=rows; p.N=512; p.K1=512; p.Hdiv=1;
    p.A1H=X.h; p.A1L=X.l; p.BH[0]=WH; p.BL[0]=WL; p.C=out; p.ldc=512;
    gemm_k<0,0,1><<<dim3(rows/128,8,1),256,SMB>>>(p);
}
static void fusion_go(Tens a,Tens bm,int rows,
                      const bf* FWH,const bf* FWL,size_t woff,
                      float* P1,float* out,bf* outH,bf* outL){
    GP p{}; p.M=rows; p.N=512; p.K1=512; p.K2=512; p.Hdiv=1;
    p.A1H=a.h; p.A1L=a.l; p.A2H=bm.h; p.A2L=bm.l;
    p.BH[0]=FWH+0*2097152+woff; p.BH[1]=FWH+1*2097152+woff;
    p.BL[0]=FWL+0*2097152+woff; p.BL[1]=FWL+1*2097152+woff;
    p.C=P1; p.ldc=512;
    gemm_k<0,0,1><<<dim3(rows/128,8,1),256,SMB>>>(p);
    p.BH[0]=FWH+2*2097152+woff; p.BH[1]=FWH+3*2097152+woff;
    p.BL[0]=FWL+2*2097152+woff; p.BL[1]=FWL+3*2097152+woff;
    p.C=out; p.CH=outH; p.CL=outL; p.E1=P1; p.E2=a.f;
    gemm_k<0,1,1><<<dim3(rows/128,8,1),256,SMB>>>(p);
}
static void attn_go(float* S,Tens q,int Nqq,Tens kv,int Nkv,
                    const bf* WH,const bf* WL,const float* a1,const float* a2,
                    const unsigned* bits,int bld,long long sb,
                    float* agg,bf* aggH,bf* aggL){
    float *projQ=S+O_PJQ,*projK=S+O_PJK;
    float *rq=S+O_EQ,*rk=S+O_EK,*q1=S+O_Q1,*k1=S+O_K1,*q2=S+O_Q2,*k2=S+O_K2;
    float *cs=S+O_CSC,*ps=S+O_PS;
    proj_go(q,NB*Nqq,WH,WL,projQ);
    proj_go(kv,NB*Nkv,WH,WL,projK);
    dot_a_k<<<(NB*HH*Nqq+255)/256,256>>>(projQ,a1,rq,q1,q2,Nqq);
    dot_a_k<<<(NB*HH*Nkv+255)/256,256>>>(projK,a2,rk,k1,k2,Nkv);
    int nch=Nqq/256;
    bitsum_k<<<dim3(Nkv/128,nch,NB),128>>>(bits,rq,q1,q2,rk,k1,k2,ps,Nqq,Nkv,bld,nch,sb);
    csmerge_k<<<(NB*HH*Nkv+255)/256,256>>>(ps,cs,Nkv,nch);
    GP p{}; p.M=Nqq; p.N=64; p.K1=Nkv; p.Hdiv=HH;
    p.B1=projK; p.ldb1=512; p.sB_b=(long long)Nkv*512; p.sB_h=64;
    p.C=agg; p.ldc=512; p.sC_b=(long long)Nqq*512; p.sC_h=64;
    p.CH=aggH; p.CL=aggL;
    p.scv=cs; p.sSc=Nkv;
    p.qr=rq; p.qe1=q1; p.qe2=q2; p.kr=rk; p.ke1=k1; p.ke2=k2;
    p.bits=bits; p.bld=bld; p.sBits_b=sb;
    gemm_k<2,2,0><<<dim3(Nqq/128,1,NB*HH),256,SMB>>>(p);
}

extern "C" void kernel_launch(void* const* d_in, const int* in_sizes, int n_in,
                              void* d_out, int out_size){
    cudaFuncSetAttribute(gemm_k<0,0,1>,cudaFuncAttributeMaxDynamicSharedMemorySize,SMB);
    cudaFuncSetAttribute(gemm_k<0,1,1>,cudaFuncAttributeMaxDynamicSharedMemorySize,SMB);
    cudaFuncSetAttribute(gemm_k<1,0,1>,cudaFuncAttributeMaxDynamicSharedMemorySize,SMB);
    cudaFuncSetAttribute(gemm_k<2,2,0>,cudaFuncAttributeMaxDynamicSharedMemorySize,SMB);
    float* S; cudaGetSymbolAddress((void**)&S, d_scratch);
    const float* in_g=(const float*)d_in[0];
    const float* in_c=(const float*)d_in[1];
    const float* in_q=(const float*)d_in[2];
    const int* adj_gc=(const int*)d_in[3];
    const int* adj_gq=(const int*)d_in[4];
    const float* aW[3]={(const float*)d_in[5],(const float*)d_in[8],(const float*)d_in[11]};
    const float* aa1[3]={(const float*)d_in[6],(const float*)d_in[9],(const float*)d_in[12]};
    const float* aa2[3]={(const float*)d_in[7],(const float*)d_in[10],(const float*)d_in[13]};
    const float* fus[4]={(const float*)d_in[14],(const float*)d_in[15],(const float*)d_in[16],(const float*)d_in[17]};
    float* out=(float*)d_out;

    unsigned* bgc=(unsigned*)(S+O_BGC);
    unsigned* bgq=(unsigned*)(S+O_BGQ);
    unsigned* bgqT=(unsigned*)(S+O_BGQT);
    bf* WTH=(bf*)(S+O_WTH); bf* WTL=(bf*)(S+O_WTL);
    bf* FWH=(bf*)(S+O_FWH); bf* FWL=(bf*)(S+O_FWL);
    #define BFP(o) ((bf*)(S+(o)))
    float *gsame=S+O_GS, *agg=S+O_AGG, *P1=S+O_P1, *G1f=S+O_G1;

    bitpack_k<<<512,256>>>(adj_gc,bgc,131072);
    bitpack_k<<<128,256>>>(adj_gq,bgq,32768);
    bitpackT_k<<<128,256>>>(adj_gq,bgqT);
    repack3_k<<<(3*2*HH*FF*DD+255)/256,256>>>(aW[0],aW[1],aW[2],WTH,WTL);
    {
        WS w{};
        for(int i=0;i<4;i++){ w.src[i]=fus[i]; w.h[i]=FWH+(size_t)i*2097152; w.l[i]=FWL+(size_t)i*2097152; w.n[i]=2097152; }
        w.src[4]=in_g; w.h[4]=BFP(O_IGH); w.l[4]=BFP(O_IGL); w.n[4]=2097152;
        w.src[5]=in_c; w.h[5]=BFP(O_ICH); w.l[5]=BFP(O_ICL); w.n[5]=2097152;
        w.src[6]=in_q; w.h[6]=BFP(O_IQH); w.l[6]=BFP(O_IQL); w.n[6]=524288;
        wsplit_all<<<dim3(8192,7),256>>>(w);
    }

    Tens GS={gsame,BFP(O_GSH),BFP(O_GSL)};
    Tens AG={agg,BFP(O_AGH),BFP(O_AGL)};
    Tens G1={G1f,BFP(O_G1H),BFP(O_G1L)};

    for(int l=0;l<2;l++){
        Tens G,C,Q; float *Gout,*Cout,*Qout; bf *GoH,*GoL,*CoH,*CoL,*QoH,*QoL;
        if(l==0){
            G={in_g,BFP(O_IGH),BFP(O_IGL)}; C={in_c,BFP(O_ICH),BFP(O_ICL)}; Q={in_q,BFP(O_IQH),BFP(O_IQL)};
            Gout=S+O_G0; Cout=S+O_C0; Qout=S+O_Q0;
            GoH=BFP(O_G0H); GoL=BFP(O_G0L); CoH=BFP(O_C0H); CoL=BFP(O_C0L); QoH=BFP(O_Q0H); QoL=BFP(O_Q0L);
        } else {
            G={S+O_G0,BFP(O_G0H),BFP(O_G0L)}; C={S+O_C0,BFP(O_C0H),BFP(O_C0L)}; Q={S+O_Q0,BFP(O_Q0H),BFP(O_Q0L)};
            Gout=out; Cout=out+SZ_GF; Qout=out+2*SZ_GF;
            GoH=GoL=CoH=CoL=QoH=QoL=nullptr;
        }
        {
            GP p{}; p.M=NC; p.N=512; p.K1=NG; p.Hdiv=1;
            p.bits=bgc; p.bld=NC/32; p.sBits_b=(long long)NG*(NC/32);
            p.BH[0]=G.h; p.BL[0]=G.l; p.sB_b=(long long)NG*512;
            p.C=gsame; p.ldc=512; p.sC_b=(long long)NC*512;
            p.CH=(bf*)GS.h; p.CL=(bf*)GS.l;
            gemm_k<1,0,1><<<dim3(NC/128,8,NB),256,SMB>>>(p);
        }
        fusion_go(C,GS,NB*NC, FWH,FWL,(size_t)(l*4+0)*262144, P1,Cout,CoH,CoL);
        attn_go(S,G,NG,C,NC, WTH+(size_t)(0*2+l)*262144, WTL+(size_t)(0*2+l)*262144,
                aa1[0]+l*HH*DD, aa2[0]+l*HH*DD, bgc,NC/32,(long long)NG*(NC/32),
                agg,(bf*)AG.h,(bf*)AG.l);
        fusion_go(G,AG,NB*NG, FWH,FWL,(size_t)(l*4+1)*262144, P1,G1f,(bf*)G1.h,(bf*)G1.l);
        attn_go(S,Q,NQ,G,NG, WTH+(size_t)(1*2+l)*262144, WTL+(size_t)(1*2+l)*262144,
                aa1[1]+l*HH*DD, aa2[1]+l*HH*DD, bgqT,NG/32,(long long)NQ*(NG/32),
                agg,(bf*)AG.h,(bf*)AG.l);
        fusion_go(Q,AG,NB*NQ, FWH,FWL,(size_t)(l*4+2)*262144, P1,Qout,QoH,QoL);
        attn_go(S,G,NG,Q,NQ, WTH+(size_t)(2*2+l)*262144, WTL+(size_t)(2*2+l)*262144,
                aa1[2]+l*HH*DD, aa2[2]+l*HH*DD, bgq,NQ/32,(long long)NG*(NQ/32),
                agg,(bf*)AG.h,(bf*)AG.l);
        fusion_go(G1,AG,NB*NG, FWH,FWL,(size_t)(l*4+3)*262144, P1,Gout,GoH,GoL);
    }
}